// round 4
// baseline (speedup 1.0000x reference)
#include <cuda_runtime.h>
#include <math.h>

// ---------------------------------------------------------------------------
// Problem constants (fixed by the reference)
// ---------------------------------------------------------------------------
namespace {
constexpr int N0     = 10000;   // nodes of omic 0 (output rows)
constexpr int NNODES = 30000;   // total nodes (NOT a multiple of 64!)
constexpr int PROJ   = 256;
constexpr int RNUM   = 6;       // relations
constexpr int HEADS1 = 4;       // layer-1 heads
constexpr int FEAT   = 128;     // H*C1 == C2 == 128
constexpr int LAB    = 5;
constexpr int EMAX   = 400000;
constexpr float SLOPE = 0.2f;
}

// ---------------------------------------------------------------------------
// Scratch (static device globals; no allocation anywhere).
// All kernels reference these directly -- kernel_launch contains ONLY kernel
// launches (no runtime API calls whatsoever).
// ---------------------------------------------------------------------------
__device__ float g_x   [(size_t)NNODES * PROJ];          // projected+concat features
__device__ float g_xw  [(size_t)RNUM * NNODES * FEAT];   // per-relation transforms (reused both layers)
__device__ float g_h   [(size_t)NNODES * FEAT];          // layer outputs (reused)
__device__ float g_qn  [(size_t)RNUM * NNODES * HEADS1]; // per-(rel,node) query logits
__device__ float g_kn  [(size_t)RNUM * NNODES * HEADS1]; // per-(rel,node) key logits
__device__ float g_alpha[(size_t)EMAX * HEADS1];         // per-edge attention logits
__device__ float g_m   [NNODES * HEADS1];                // segment max
__device__ float g_s   [NNODES * HEADS1];                // segment sum of exp
__device__ float g_agg [NNODES * FEAT];                  // unnormalized aggregation

// ---------------------------------------------------------------------------
// Helpers
// ---------------------------------------------------------------------------
__device__ __forceinline__ void atomicMaxFloat(float* addr, float value) {
    if (value >= 0.f)
        atomicMax((int*)addr, __float_as_int(value));
    else
        atomicMin((unsigned int*)addr, __float_as_uint(value));
}

// ---------------------------------------------------------------------------
// Projection GEMM: g_x[row_off+m, :] = relu(A[m,:] @ W^T + b).
// A [M,K] row-major, W [PROJ,K] row-major. 64x64x16 tile, 256 threads, 4x4/thr.
// ---------------------------------------------------------------------------
__global__ void gemm_proj_relu(const float* __restrict__ A,
                               const float* __restrict__ W,
                               const float* __restrict__ bias,
                               int M, int K, int row_off) {
    constexpr int BM = 64, BN = 64, BK = 16;
    __shared__ float As[BK][BM + 4];
    __shared__ float Bs[BK][BN + 4];

    const int m0 = blockIdx.x * BM;
    const int n0 = blockIdx.y * BN;
    const int tid = threadIdx.x;
    const int tx = tid & 15, ty = tid >> 4;

    float acc[4][4];
#pragma unroll
    for (int i = 0; i < 4; i++)
#pragma unroll
        for (int j = 0; j < 4; j++) acc[i][j] = 0.f;

    const int r  = tid >> 2;          // 0..63
    const int kq = (tid & 3) * 4;     // 0,4,8,12

    for (int k0 = 0; k0 < K; k0 += BK) {
#pragma unroll
        for (int i = 0; i < 4; i++) {
            const int kk = kq + i;
            const int gk = k0 + kk;
            float va = 0.f, vb = 0.f;
            if (m0 + r < M && gk < K) va = A[(size_t)(m0 + r) * K + gk];
            if (gk < K)               vb = W[(size_t)(n0 + r) * K + gk];
            As[kk][r] = va;
            Bs[kk][r] = vb;
        }
        __syncthreads();
#pragma unroll
        for (int kk = 0; kk < BK; kk++) {
            const float4 a4 = *(const float4*)&As[kk][ty * 4];
            const float4 b4 = *(const float4*)&Bs[kk][tx * 4];
            const float a[4] = {a4.x, a4.y, a4.z, a4.w};
            const float b[4] = {b4.x, b4.y, b4.z, b4.w};
#pragma unroll
            for (int i = 0; i < 4; i++)
#pragma unroll
                for (int j = 0; j < 4; j++) acc[i][j] += a[i] * b[j];
        }
        __syncthreads();
    }

#pragma unroll
    for (int i = 0; i < 4; i++) {
        const int row = m0 + ty * 4 + i;
        if (row >= M) continue;
#pragma unroll
        for (int j = 0; j < 4; j++) {
            const int col = n0 + tx * 4 + j;
            float v = acc[i][j] + bias[col];
            g_x[(size_t)(row_off + row) * PROJ + col] = v > 0.f ? v : 0.f;
        }
    }
}

// ---------------------------------------------------------------------------
// Per-relation GEMM: g_xw[r] = A @ W[r].  A is g_x (layer 1) or g_h (layer 2),
// selected by `layer`. W[r] is [K, FEAT] row-major. blockIdx.z = relation.
// K multiple of 16, FEAT = 128, M = NNODES (ceil-div grid + row guards).
// ---------------------------------------------------------------------------
__global__ void gemm_rel(const float* __restrict__ Wall, int K, int layer) {
    constexpr int BM = 64, BN = 64, BK = 16;
    __shared__ float As[BK][BM + 4];
    __shared__ float Bs[BK][BN + 4];

    const float* __restrict__ A = (layer == 1) ? g_x : g_h;
    const int m0 = blockIdx.x * BM;
    const int n0 = blockIdx.y * BN;
    const int rrel = blockIdx.z;
    const float* W = Wall + (size_t)rrel * K * FEAT;
    float* C = g_xw + (size_t)rrel * NNODES * FEAT;

    const int tid = threadIdx.x;
    const int tx = tid & 15, ty = tid >> 4;

    float acc[4][4];
#pragma unroll
    for (int i = 0; i < 4; i++)
#pragma unroll
        for (int j = 0; j < 4; j++) acc[i][j] = 0.f;

    const int ra  = tid >> 2;            // A tile row 0..63
    const int kqa = (tid & 3) * 4;       // A tile k group
    const int kb  = tid >> 4;            // B tile k row 0..15
    const int cb  = (tid & 15) * 4;      // B tile col group

    for (int k0 = 0; k0 < K; k0 += BK) {
#pragma unroll
        for (int i = 0; i < 4; i++) {
            const int kk = kqa + i;
            As[kk][ra] = (m0 + ra < NNODES)
                       ? A[(size_t)(m0 + ra) * K + k0 + kk] : 0.f;
        }
        const float4 b4 = *(const float4*)&W[(size_t)(k0 + kb) * FEAT + n0 + cb];
        *(float4*)&Bs[kb][cb] = b4;
        __syncthreads();
#pragma unroll
        for (int kk = 0; kk < BK; kk++) {
            const float4 a4 = *(const float4*)&As[kk][ty * 4];
            const float4 bb = *(const float4*)&Bs[kk][tx * 4];
            const float a[4] = {a4.x, a4.y, a4.z, a4.w};
            const float b[4] = {bb.x, bb.y, bb.z, bb.w};
#pragma unroll
            for (int i = 0; i < 4; i++)
#pragma unroll
                for (int j = 0; j < 4; j++) acc[i][j] += a[i] * b[j];
        }
        __syncthreads();
    }

#pragma unroll
    for (int i = 0; i < 4; i++) {
        const int row = m0 + ty * 4 + i;
        if (row >= NNODES) continue;
#pragma unroll
        for (int j = 0; j < 4; j++)
            C[(size_t)row * FEAT + n0 + tx * 4 + j] = acc[i][j];
    }
}

// ---------------------------------------------------------------------------
// qn/kn: per (relation,node) row of g_xw, dot with q[:,h] and k[:,h].
// One warp per row. q,k are [FEAT, H] row-major.
// ---------------------------------------------------------------------------
template <int H>
__global__ void qk_kernel(const float* __restrict__ q,
                          const float* __restrict__ k,
                          int nrows) {
    const int wid  = (blockIdx.x * blockDim.x + threadIdx.x) >> 5;
    const int lane = threadIdx.x & 31;
    if (wid >= nrows) return;
    const float4 v = *(const float4*)&g_xw[(size_t)wid * FEAT + lane * 4];
    const int o0 = lane * 4;
#pragma unroll
    for (int h = 0; h < H; h++) {
        float qa = v.x * q[(o0 + 0) * H + h] + v.y * q[(o0 + 1) * H + h] +
                   v.z * q[(o0 + 2) * H + h] + v.w * q[(o0 + 3) * H + h];
        float ka = v.x * k[(o0 + 0) * H + h] + v.y * k[(o0 + 1) * H + h] +
                   v.z * k[(o0 + 2) * H + h] + v.w * k[(o0 + 3) * H + h];
#pragma unroll
        for (int off = 16; off > 0; off >>= 1) {
            qa += __shfl_down_sync(0xffffffffu, qa, off);
            ka += __shfl_down_sync(0xffffffffu, ka, off);
        }
        if (lane == 0) {
            g_qn[(size_t)wid * H + h] = qa;
            g_kn[(size_t)wid * H + h] = ka;
        }
    }
}

// ---------------------------------------------------------------------------
// Reset m/s/agg each layer.
// ---------------------------------------------------------------------------
__global__ void init_kernel() {
    const int i = blockIdx.x * blockDim.x + threadIdx.x;
    if (i < NNODES * HEADS1) {
        g_m[i] = -INFINITY;
        g_s[i] = 0.f;
    }
    if (i < NNODES * FEAT) g_agg[i] = 0.f;
}

// ---------------------------------------------------------------------------
// Pass A: per-edge logits + segment max (atomicMax).
// ---------------------------------------------------------------------------
template <int H>
__global__ void edge_max(const int* __restrict__ src,
                         const int* __restrict__ dst,
                         const int* __restrict__ et,
                         int E, int dst_limit) {
    const int e = blockIdx.x * blockDim.x + threadIdx.x;
    if (e >= E) return;
    const int d = dst[e];
    if (d >= dst_limit) return;
    const int s = src[e];
    const int t = et[e];
    const size_t bq = ((size_t)t * NNODES + d) * H;
    const size_t bk = ((size_t)t * NNODES + s) * H;
#pragma unroll
    for (int h = 0; h < H; h++) {
        float al = g_qn[bq + h] + g_kn[bk + h];
        al = al > 0.f ? al : SLOPE * al;
        g_alpha[(size_t)e * H + h] = al;
        atomicMaxFloat(&g_m[d * H + h], al);
    }
}

// ---------------------------------------------------------------------------
// Pass B: a = exp(alpha - m[dst]); s[dst] += a; agg[dst] += a * xw[etype,src].
// One warp per edge, each lane handles 4 consecutive features (float4).
// Head of feature o is o/32 (H=4) or 0 (H=1).
// ---------------------------------------------------------------------------
template <int H>
__global__ void edge_scatter(const int* __restrict__ src,
                             const int* __restrict__ dst,
                             const int* __restrict__ et,
                             int E, int dst_limit) {
    const int e = (blockIdx.x * blockDim.x + threadIdx.x) >> 5;
    const int lane = threadIdx.x & 31;
    if (e >= E) return;
    const int d = dst[e];
    if (d >= dst_limit) return;
    const int s = src[e];
    const int t = et[e];
    const int h = (H == 1) ? 0 : (lane >> 3);
    const float a = expf(g_alpha[(size_t)e * H + h] - g_m[d * H + h]);
    if (((H == 1) && lane == 0) || ((H == 4) && (lane & 7) == 0))
        atomicAdd(&g_s[d * H + h], a);
    const float4 v = *(const float4*)&g_xw[((size_t)t * NNODES + s) * FEAT + lane * 4];
    float* aggp = &g_agg[(size_t)d * FEAT + lane * 4];
    atomicAdd(aggp + 0, a * v.x);
    atomicAdd(aggp + 1, a * v.y);
    atomicAdd(aggp + 2, a * v.z);
    atomicAdd(aggp + 3, a * v.w);
}

// ---------------------------------------------------------------------------
// Normalize + bias + relu -> g_h [nn, FEAT]
// ---------------------------------------------------------------------------
template <int H>
__global__ void normalize_kernel(const float* __restrict__ bias, int nn) {
    const int i = blockIdx.x * blockDim.x + threadIdx.x;
    if (i >= nn * FEAT) return;
    const int n = i >> 7;         // /FEAT
    const int o = i & 127;
    const int h = (H == 1) ? 0 : (o >> 5);
    float v = g_agg[i] / (g_s[n * H + h] + 1e-16f) + bias[o];
    g_h[i] = v > 0.f ? v : 0.f;
}

// ---------------------------------------------------------------------------
// Final classifier: out[n,l] = g_h[n,:] . Wl[l,:] + bl[l]  for n < N0.
// One warp per node.
// ---------------------------------------------------------------------------
__global__ void final_kernel(const float* __restrict__ Wl,
                             const float* __restrict__ bl,
                             float* __restrict__ out) {
    const int n = (blockIdx.x * blockDim.x + threadIdx.x) >> 5;
    const int lane = threadIdx.x & 31;
    if (n >= N0) return;
    const float4 v = *(const float4*)&g_h[(size_t)n * FEAT + lane * 4];
#pragma unroll
    for (int l = 0; l < LAB; l++) {
        const float4 w = *(const float4*)&Wl[l * FEAT + lane * 4];
        float p = v.x * w.x + v.y * w.y + v.z * w.z + v.w * w.w;
#pragma unroll
        for (int off = 16; off > 0; off >>= 1)
            p += __shfl_down_sync(0xffffffffu, p, off);
        if (lane == 0) out[n * LAB + l] = p + bl[l];
    }
}

// ---------------------------------------------------------------------------
// Launcher: ONLY kernel launches. No runtime API calls of any kind.
// ---------------------------------------------------------------------------
extern "C" void kernel_launch(void* const* d_in, const int* in_sizes, int n_in,
                              void* d_out, int out_size) {
    const float* x0  = (const float*)d_in[0];
    const float* x1  = (const float*)d_in[1];
    const float* x2  = (const float*)d_in[2];
    const int*   ei  = (const int*)  d_in[3];
    const int*   et  = (const int*)  d_in[4];
    const float* Wp0 = (const float*)d_in[5];
    const float* bp0 = (const float*)d_in[6];
    const float* Wp1 = (const float*)d_in[7];
    const float* bp1 = (const float*)d_in[8];
    const float* Wp2 = (const float*)d_in[9];
    const float* bp2 = (const float*)d_in[10];
    const float* W1  = (const float*)d_in[11];
    const float* q1  = (const float*)d_in[12];
    const float* k1  = (const float*)d_in[13];
    const float* b1  = (const float*)d_in[14];
    const float* W2  = (const float*)d_in[15];
    const float* q2  = (const float*)d_in[16];
    const float* k2  = (const float*)d_in[17];
    const float* b2  = (const float*)d_in[18];
    const float* Wl  = (const float*)d_in[19];
    const float* bl  = (const float*)d_in[20];
    float* out = (float*)d_out;

    const int E = in_sizes[4];          // 400000
    const int* srcp = ei;
    const int* dstp = ei + E;

    const int TPB = 256;

    // --- projections: relu(x_i @ Wp_i^T + bp_i) -> g_x rows ---
    {
        dim3 g0((N0 + 63) / 64, PROJ / 64);
        gemm_proj_relu<<<g0, TPB>>>(x0, Wp0, bp0, N0, 2000, 0);
        gemm_proj_relu<<<g0, TPB>>>(x1, Wp1, bp1, N0, 1500, N0);
        gemm_proj_relu<<<g0, TPB>>>(x2, Wp2, bp2, N0, 1000, 2 * N0);
    }

    const int nrows = RNUM * NNODES;
    const int qk_blocks = (nrows * 32 + TPB - 1) / TPB;
    const int init_blocks = (NNODES * FEAT + TPB - 1) / TPB;
    const int ea_blocks = (E + TPB - 1) / TPB;
    const int eb_blocks = (E * 32 + TPB - 1) / TPB;

    // --- layer 1 ---
    {
        dim3 g((NNODES + 63) / 64, FEAT / 64, RNUM);   // ceil-div: 30000 % 64 != 0
        gemm_rel<<<g, TPB>>>(W1, PROJ, 1);
    }
    qk_kernel<HEADS1><<<qk_blocks, TPB>>>(q1, k1, nrows);
    init_kernel<<<init_blocks, TPB>>>();
    edge_max<HEADS1><<<ea_blocks, TPB>>>(srcp, dstp, et, E, NNODES);
    edge_scatter<HEADS1><<<eb_blocks, TPB>>>(srcp, dstp, et, E, NNODES);
    normalize_kernel<HEADS1><<<(NNODES * FEAT + TPB - 1) / TPB, TPB>>>(b1, NNODES);

    // --- layer 2 (only dst < N0 matter for the final classifier) ---
    {
        dim3 g((NNODES + 63) / 64, FEAT / 64, RNUM);   // ceil-div
        gemm_rel<<<g, TPB>>>(W2, FEAT, 2);
    }
    qk_kernel<1><<<qk_blocks, TPB>>>(q2, k2, nrows);
    init_kernel<<<init_blocks, TPB>>>();
    edge_max<1><<<ea_blocks, TPB>>>(srcp, dstp, et, E, N0);
    edge_scatter<1><<<eb_blocks, TPB>>>(srcp, dstp, et, E, N0);
    normalize_kernel<1><<<(N0 * FEAT + TPB - 1) / TPB, TPB>>>(b2, N0);

    // --- classifier ---
    final_kernel<<<(N0 * 32 + TPB - 1) / TPB, TPB>>>(Wl, bl, out);
}

// round 6
// speedup vs baseline: 1.3898x; 1.3898x over previous
#include <cuda_runtime.h>
#include <math.h>
#include <mma.h>

using namespace nvcuda;

// ---------------------------------------------------------------------------
// Problem constants (fixed by the reference)
// ---------------------------------------------------------------------------
namespace {
constexpr int N0     = 10000;   // nodes of omic 0 (output rows)
constexpr int NNODES = 30000;   // total nodes (NOT a multiple of tile size!)
constexpr int PROJ   = 256;
constexpr int RNUM   = 6;       // relations
constexpr int HEADS1 = 4;       // layer-1 heads
constexpr int FEAT   = 128;     // H*C1 == C2 == 128
constexpr int LAB    = 5;
constexpr int EMAX   = 400000;
constexpr float SLOPE = 0.2f;
}

// ---------------------------------------------------------------------------
// Scratch (static device globals; no allocation anywhere).
// ---------------------------------------------------------------------------
__device__ float g_x   [(size_t)NNODES * PROJ];          // projected+concat features
__device__ float g_xw  [(size_t)RNUM * NNODES * FEAT];   // per-relation transforms
__device__ float g_h   [(size_t)NNODES * FEAT];          // layer outputs (reused)
__device__ float g_qn  [(size_t)RNUM * NNODES * HEADS1];
__device__ float g_kn  [(size_t)RNUM * NNODES * HEADS1];
__device__ float g_alpha[(size_t)EMAX * HEADS1];
__device__ float g_m   [NNODES * HEADS1];
__device__ float g_s   [NNODES * HEADS1];
__device__ float g_agg [NNODES * FEAT];

// ---------------------------------------------------------------------------
// Helpers
// ---------------------------------------------------------------------------
__device__ __forceinline__ void atomicMaxFloat(float* addr, float value) {
    if (value >= 0.f)
        atomicMax((int*)addr, __float_as_int(value));
    else
        atomicMin((unsigned int*)addr, __float_as_uint(value));
}

// ---------------------------------------------------------------------------
// TF32 tensor-core GEMM, 128x64 block tile, BK=32, 256 threads (8 warps).
// Each warp computes a 32x32 tile = 2x2 wmma m16n16k8 fragments.
//
// MODE 0 (rel):  A = g_x (layer==1) or g_h (layer==2), [M,K] row-major.
//                B = Wall + blockIdx.z * K*FEAT, [K,FEAT] row-major.
//                C = g_xw + blockIdx.z * NNODES*FEAT, plain store.
// MODE 1 (proj): A = Aglob [M,K] row-major.  B = Wall [256,K] row-major
//                (used transposed).  C = g_x + row_off rows, bias+ReLU.
// ---------------------------------------------------------------------------
template <int MODE>
__global__ void gemm_tf32(const float* __restrict__ Aglob,
                          const float* __restrict__ Wall,
                          const float* __restrict__ bias,
                          int M, int K, int row_off, int layer) {
    constexpr int BM = 128, BN = 64, BK = 32;
    constexpr int LDA = BK + 4;    // 36 floats (multiple of 4)
    constexpr int LDB = BN + 4;    // 68 floats (multiple of 4)
    constexpr int LDC = BN + 4;    // 68

    // One shared arena, aliased: [As | Bs] during mainloop, Cs afterwards.
    __shared__ __align__(16) float smem[BM * LDC];          // 8704 floats = 34816 B
    float (*As)[LDA] = reinterpret_cast<float(*)[LDA]>(smem);          // 128*36 = 4608
    float (*Bs)[LDB] = reinterpret_cast<float(*)[LDB]>(smem + BM*LDA); // 32*68  = 2176
    float* Cs = smem;

    const int tid = threadIdx.x;
    const int wid = tid >> 5;
    const int warp_m = wid & 3;      // 0..3  -> 32-row slab
    const int warp_n = wid >> 2;     // 0..1  -> 32-col slab

    const int m0 = blockIdx.x * BM;
    const int n0 = blockIdx.y * BN;

    const float* A = Aglob;
    const float* B = Wall;
    if (MODE == 0) {
        A = (layer == 1) ? g_x : g_h;
        B = Wall + (size_t)blockIdx.z * K * FEAT;
    }

    wmma::fragment<wmma::accumulator, 16, 16, 8, float> cf[2][2];
#pragma unroll
    for (int i = 0; i < 2; i++)
#pragma unroll
        for (int j = 0; j < 2; j++) wmma::fill_fragment(cf[i][j], 0.f);

    for (int k0 = 0; k0 < K; k0 += BK) {
        // ---- load A tile: 128x32 = 1024 float4, 4 per thread ----
#pragma unroll
        for (int i = 0; i < 4; i++) {
            const int f = tid + i * 256;          // 0..1023
            const int r  = f >> 3;                // row in tile
            const int kq = (f & 7) * 4;           // k offset (float4)
            const int grow = m0 + r;
            const int gk   = k0 + kq;
            float4 v = make_float4(0.f, 0.f, 0.f, 0.f);
            if (grow < M && gk < K)               // K % 4 == 0 -> no straddle
                v = *(const float4*)&A[(size_t)grow * K + gk];
            *(float4*)&As[r][kq] = v;
        }
        // ---- load B tile: 32x64 ----
        if (MODE == 0) {
            // B [K, FEAT] row-major: straight copy. 512 float4, 2 per thread.
#pragma unroll
            for (int i = 0; i < 2; i++) {
                const int f = tid + i * 256;      // 0..511
                const int kk = f >> 4;            // 0..31
                const int cb = (f & 15) * 4;      // 0..60
                const int gk = k0 + kk;
                float4 v = make_float4(0.f, 0.f, 0.f, 0.f);
                if (gk < K)
                    v = *(const float4*)&B[(size_t)gk * FEAT + n0 + cb];
                *(float4*)&Bs[kk][cb] = v;
            }
        } else {
            // B = W [256, K] row-major, used transposed: Bs[k][n] = W[n0+n][k0+k].
#pragma unroll
            for (int i = 0; i < 2; i++) {
                const int f = tid + i * 256;      // 0..511
                const int n  = f >> 3;            // 0..63
                const int kq = (f & 7) * 4;       // 0..28
                const int gk = k0 + kq;
                float4 v = make_float4(0.f, 0.f, 0.f, 0.f);
                if (gk < K)
                    v = *(const float4*)&B[(size_t)(n0 + n) * K + gk];
                Bs[kq + 0][n] = v.x;
                Bs[kq + 1][n] = v.y;
                Bs[kq + 2][n] = v.z;
                Bs[kq + 3][n] = v.w;
            }
        }
        __syncthreads();

        // ---- 4 k-substeps of 8 ----
#pragma unroll
        for (int ks = 0; ks < 4; ks++) {
            wmma::fragment<wmma::matrix_a, 16, 16, 8, wmma::precision::tf32,
                           wmma::row_major> af[2];
            wmma::fragment<wmma::matrix_b, 16, 16, 8, wmma::precision::tf32,
                           wmma::row_major> bf[2];
#pragma unroll
            for (int i = 0; i < 2; i++) {
                wmma::load_matrix_sync(af[i], &As[warp_m * 32 + i * 16][ks * 8], LDA);
#pragma unroll
                for (int t = 0; t < af[i].num_elements; t++)
                    af[i].x[t] = wmma::__float_to_tf32(af[i].x[t]);
            }
#pragma unroll
            for (int j = 0; j < 2; j++) {
                wmma::load_matrix_sync(bf[j], &Bs[ks * 8][warp_n * 32 + j * 16], LDB);
#pragma unroll
                for (int t = 0; t < bf[j].num_elements; t++)
                    bf[j].x[t] = wmma::__float_to_tf32(bf[j].x[t]);
            }
#pragma unroll
            for (int i = 0; i < 2; i++)
#pragma unroll
                for (int j = 0; j < 2; j++)
                    wmma::mma_sync(cf[i][j], af[i], bf[j], cf[i][j]);
        }
        __syncthreads();
    }

    // ---- stage C through shared, then guarded epilogue ----
#pragma unroll
    for (int i = 0; i < 2; i++)
#pragma unroll
        for (int j = 0; j < 2; j++)
            wmma::store_matrix_sync(&Cs[(warp_m * 32 + i * 16) * LDC +
                                        warp_n * 32 + j * 16],
                                    cf[i][j], LDC, wmma::mem_row_major);
    __syncthreads();

#pragma unroll
    for (int i = 0; i < 32; i++) {
        const int idx = tid + i * 256;            // 0..8191
        const int r = idx >> 6;                   // /64
        const int c = idx & 63;
        const int grow = m0 + r;
        if (grow >= M) continue;
        const float acc = Cs[r * LDC + c];
        if (MODE == 1) {
            float v = acc + bias[n0 + c];
            g_x[(size_t)(row_off + grow) * PROJ + n0 + c] = v > 0.f ? v : 0.f;
        } else {
            float* C = g_xw + (size_t)blockIdx.z * NNODES * FEAT;
            C[(size_t)grow * FEAT + n0 + c] = acc;
        }
    }
}

// ---------------------------------------------------------------------------
// qn/kn: per (relation,node) row of g_xw, dot with q[:,h] and k[:,h].
// One warp per row. q,k are [FEAT, H] row-major.
// ---------------------------------------------------------------------------
template <int H>
__global__ void qk_kernel(const float* __restrict__ q,
                          const float* __restrict__ k,
                          int nrows) {
    const int wid  = (blockIdx.x * blockDim.x + threadIdx.x) >> 5;
    const int lane = threadIdx.x & 31;
    if (wid >= nrows) return;
    const float4 v = *(const float4*)&g_xw[(size_t)wid * FEAT + lane * 4];
    const int o0 = lane * 4;
#pragma unroll
    for (int h = 0; h < H; h++) {
        float qa = v.x * q[(o0 + 0) * H + h] + v.y * q[(o0 + 1) * H + h] +
                   v.z * q[(o0 + 2) * H + h] + v.w * q[(o0 + 3) * H + h];
        float ka = v.x * k[(o0 + 0) * H + h] + v.y * k[(o0 + 1) * H + h] +
                   v.z * k[(o0 + 2) * H + h] + v.w * k[(o0 + 3) * H + h];
#pragma unroll
        for (int off = 16; off > 0; off >>= 1) {
            qa += __shfl_down_sync(0xffffffffu, qa, off);
            ka += __shfl_down_sync(0xffffffffu, ka, off);
        }
        if (lane == 0) {
            g_qn[(size_t)wid * H + h] = qa;
            g_kn[(size_t)wid * H + h] = ka;
        }
    }
}

// ---------------------------------------------------------------------------
// Reset m/s/agg each layer.
// ---------------------------------------------------------------------------
__global__ void init_kernel() {
    const int i = blockIdx.x * blockDim.x + threadIdx.x;
    if (i < NNODES * HEADS1) {
        g_m[i] = -INFINITY;
        g_s[i] = 0.f;
    }
    if (i < NNODES * FEAT) g_agg[i] = 0.f;
}

// ---------------------------------------------------------------------------
// Pass A: per-edge logits + segment max (atomicMax).
// ---------------------------------------------------------------------------
template <int H>
__global__ void edge_max(const int* __restrict__ src,
                         const int* __restrict__ dst,
                         const int* __restrict__ et,
                         int E, int dst_limit) {
    const int e = blockIdx.x * blockDim.x + threadIdx.x;
    if (e >= E) return;
    const int d = dst[e];
    if (d >= dst_limit) return;
    const int s = src[e];
    const int t = et[e];
    const size_t bq = ((size_t)t * NNODES + d) * H;
    const size_t bk = ((size_t)t * NNODES + s) * H;
#pragma unroll
    for (int h = 0; h < H; h++) {
        float al = g_qn[bq + h] + g_kn[bk + h];
        al = al > 0.f ? al : SLOPE * al;
        g_alpha[(size_t)e * H + h] = al;
        atomicMaxFloat(&g_m[d * H + h], al);
    }
}

// ---------------------------------------------------------------------------
// Pass B: a = exp(alpha - m[dst]); s[dst] += a; agg[dst] += a * xw[etype,src].
// One warp per edge, each lane handles 4 consecutive features (float4).
// ---------------------------------------------------------------------------
template <int H>
__global__ void edge_scatter(const int* __restrict__ src,
                             const int* __restrict__ dst,
                             const int* __restrict__ et,
                             int E, int dst_limit) {
    const int e = (blockIdx.x * blockDim.x + threadIdx.x) >> 5;
    const int lane = threadIdx.x & 31;
    if (e >= E) return;
    const int d = dst[e];
    if (d >= dst_limit) return;
    const int s = src[e];
    const int t = et[e];
    const int h = (H == 1) ? 0 : (lane >> 3);
    const float a = expf(g_alpha[(size_t)e * H + h] - g_m[d * H + h]);
    if (((H == 1) && lane == 0) || ((H == 4) && (lane & 7) == 0))
        atomicAdd(&g_s[d * H + h], a);
    const float4 v = *(const float4*)&g_xw[((size_t)t * NNODES + s) * FEAT + lane * 4];
    float* aggp = &g_agg[(size_t)d * FEAT + lane * 4];
    atomicAdd(aggp + 0, a * v.x);
    atomicAdd(aggp + 1, a * v.y);
    atomicAdd(aggp + 2, a * v.z);
    atomicAdd(aggp + 3, a * v.w);
}

// ---------------------------------------------------------------------------
// Normalize + bias + relu -> g_h [nn, FEAT]
// ---------------------------------------------------------------------------
template <int H>
__global__ void normalize_kernel(const float* __restrict__ bias, int nn) {
    const int i = blockIdx.x * blockDim.x + threadIdx.x;
    if (i >= nn * FEAT) return;
    const int n = i >> 7;
    const int o = i & 127;
    const int h = (H == 1) ? 0 : (o >> 5);
    float v = g_agg[i] / (g_s[n * H + h] + 1e-16f) + bias[o];
    g_h[i] = v > 0.f ? v : 0.f;
}

// ---------------------------------------------------------------------------
// Final classifier: out[n,l] = g_h[n,:] . Wl[l,:] + bl[l]  for n < N0.
// ---------------------------------------------------------------------------
__global__ void final_kernel(const float* __restrict__ Wl,
                             const float* __restrict__ bl,
                             float* __restrict__ out) {
    const int n = (blockIdx.x * blockDim.x + threadIdx.x) >> 5;
    const int lane = threadIdx.x & 31;
    if (n >= N0) return;
    const float4 v = *(const float4*)&g_h[(size_t)n * FEAT + lane * 4];
#pragma unroll
    for (int l = 0; l < LAB; l++) {
        const float4 w = *(const float4*)&Wl[l * FEAT + lane * 4];
        float p = v.x * w.x + v.y * w.y + v.z * w.z + v.w * w.w;
#pragma unroll
        for (int off = 16; off > 0; off >>= 1)
            p += __shfl_down_sync(0xffffffffu, p, off);
        if (lane == 0) out[n * LAB + l] = p + bl[l];
    }
}

// ---------------------------------------------------------------------------
// Launcher: ONLY kernel launches.
// ---------------------------------------------------------------------------
extern "C" void kernel_launch(void* const* d_in, const int* in_sizes, int n_in,
                              void* d_out, int out_size) {
    const float* x0  = (const float*)d_in[0];
    const float* x1  = (const float*)d_in[1];
    const float* x2  = (const float*)d_in[2];
    const int*   ei  = (const int*)  d_in[3];
    const int*   et  = (const int*)  d_in[4];
    const float* Wp0 = (const float*)d_in[5];
    const float* bp0 = (const float*)d_in[6];
    const float* Wp1 = (const float*)d_in[7];
    const float* bp1 = (const float*)d_in[8];
    const float* Wp2 = (const float*)d_in[9];
    const float* bp2 = (const float*)d_in[10];
    const float* W1  = (const float*)d_in[11];
    const float* q1  = (const float*)d_in[12];
    const float* k1  = (const float*)d_in[13];
    const float* b1  = (const float*)d_in[14];
    const float* W2  = (const float*)d_in[15];
    const float* q2  = (const float*)d_in[16];
    const float* k2  = (const float*)d_in[17];
    const float* b2  = (const float*)d_in[18];
    const float* Wl  = (const float*)d_in[19];
    const float* bl  = (const float*)d_in[20];
    float* out = (float*)d_out;

    const int E = in_sizes[4];          // 400000
    const int* srcp = ei;
    const int* dstp = ei + E;

    const int TPB = 256;

    // --- projections (tf32 tensor cores): relu(x_i @ Wp_i^T + bp_i) -> g_x ---
    {
        dim3 g((N0 + 127) / 128, PROJ / 64);
        gemm_tf32<1><<<g, TPB>>>(x0, Wp0, bp0, N0, 2000, 0,      0);
        gemm_tf32<1><<<g, TPB>>>(x1, Wp1, bp1, N0, 1500, N0,     0);
        gemm_tf32<1><<<g, TPB>>>(x2, Wp2, bp2, N0, 1000, 2 * N0, 0);
    }

    const int nrows = RNUM * NNODES;
    const int qk_blocks = (nrows * 32 + TPB - 1) / TPB;
    const int init_blocks = (NNODES * FEAT + TPB - 1) / TPB;
    const int ea_blocks = (E + TPB - 1) / TPB;
    const int eb_blocks = (E * 32 + TPB - 1) / TPB;

    // --- layer 1 ---
    {
        dim3 g((NNODES + 127) / 128, FEAT / 64, RNUM);
        gemm_tf32<0><<<g, TPB>>>(nullptr, W1, nullptr, NNODES, PROJ, 0, 1);
    }
    qk_kernel<HEADS1><<<qk_blocks, TPB>>>(q1, k1, nrows);
    init_kernel<<<init_blocks, TPB>>>();
    edge_max<HEADS1><<<ea_blocks, TPB>>>(srcp, dstp, et, E, NNODES);
    edge_scatter<HEADS1><<<eb_blocks, TPB>>>(srcp, dstp, et, E, NNODES);
    normalize_kernel<HEADS1><<<(NNODES * FEAT + TPB - 1) / TPB, TPB>>>(b1, NNODES);

    // --- layer 2 (only dst < N0 matter for the final classifier) ---
    {
        dim3 g((NNODES + 127) / 128, FEAT / 64, RNUM);
        gemm_tf32<0><<<g, TPB>>>(nullptr, W2, nullptr, NNODES, FEAT, 0, 2);
    }
    qk_kernel<1><<<qk_blocks, TPB>>>(q2, k2, nrows);
    init_kernel<<<init_blocks, TPB>>>();
    edge_max<1><<<ea_blocks, TPB>>>(srcp, dstp, et, E, N0);
    edge_scatter<1><<<eb_blocks, TPB>>>(srcp, dstp, et, E, N0);
    normalize_kernel<1><<<(N0 * FEAT + TPB - 1) / TPB, TPB>>>(b2, N0);

    // --- classifier ---
    final_kernel<<<(N0 * 32 + TPB - 1) / TPB, TPB>>>(Wl, bl, out);
}

// round 7
// speedup vs baseline: 1.4882x; 1.0707x over previous
#include <cuda_runtime.h>
#include <math.h>
#include <mma.h>

using namespace nvcuda;

// ---------------------------------------------------------------------------
// Problem constants (fixed by the reference)
// ---------------------------------------------------------------------------
namespace {
constexpr int N0     = 10000;   // nodes of omic 0 (output rows)
constexpr int NNODES = 30000;   // total nodes
constexpr int PROJ   = 256;
constexpr int RNUM   = 6;       // relations
constexpr int HEADS1 = 4;       // layer-1 heads
constexpr int FEAT   = 128;     // H*C1 == C2 == 128
constexpr int LAB    = 5;
constexpr int EMAX   = 400000;
constexpr float SLOPE = 0.2f;
}

// ---------------------------------------------------------------------------
// Scratch (static device globals; no allocation anywhere).
// ---------------------------------------------------------------------------
__device__ float g_x   [(size_t)NNODES * PROJ];
__device__ float g_xw  [(size_t)RNUM * NNODES * FEAT];
__device__ float g_h   [(size_t)NNODES * FEAT];
__device__ float g_qn  [(size_t)RNUM * NNODES * HEADS1];
__device__ float g_kn  [(size_t)RNUM * NNODES * HEADS1];
__device__ float g_alpha[(size_t)EMAX * HEADS1];
__device__ float g_m   [NNODES * HEADS1];
__device__ float g_s   [NNODES * HEADS1];
__device__ float g_agg [NNODES * FEAT];

// ---------------------------------------------------------------------------
// Helpers
// ---------------------------------------------------------------------------
__device__ __forceinline__ void atomicMaxFloat(float* addr, float value) {
    if (value >= 0.f)
        atomicMax((int*)addr, __float_as_int(value));
    else
        atomicMin((unsigned int*)addr, __float_as_uint(value));
}

__device__ __forceinline__ void red_add_v4(float* addr, float a, float b,
                                           float c, float d) {
    asm volatile("red.global.add.v4.f32 [%0], {%1, %2, %3, %4};"
                 :: "l"(addr), "f"(a), "f"(b), "f"(c), "f"(d) : "memory");
}

// ---------------------------------------------------------------------------
// TF32 tensor-core GEMM, 128x64 block tile, BK=32, 256 threads (8 warps).
// Each warp computes a 32x32 tile = 2x2 wmma m16n16k8 fragments.
// tf32 conversion happens ONCE at smem store; register-prefetch pipeline
// overlaps next-tile global loads with the mma substeps; interior MODE-0
// blocks store accumulators straight to global (no smem C staging).
//
// MODE 0 (rel):  A = g_x (layer==1) or g_h (layer==2), [M,K] row-major.
//                B = Wall + blockIdx.z * K*FEAT, [K,FEAT] row-major.
//                C = g_xw + blockIdx.z * NNODES*FEAT, plain store.
// MODE 1 (proj): A = Aglob [M,K] row-major.  B = Wall [256,K] row-major
//                (used transposed).  C = g_x + row_off rows, bias+ReLU.
// ---------------------------------------------------------------------------
template <int MODE>
__global__ void __launch_bounds__(256, 2)
gemm_tf32(const float* __restrict__ Aglob,
          const float* __restrict__ Wall,
          const float* __restrict__ bias,
          int M, int K, int row_off, int layer) {
    constexpr int BM = 128, BN = 64, BK = 32;
    constexpr int LDA = BK + 4;    // 36
    constexpr int LDB = BN + 4;    // 68
    constexpr int LDC = BN + 4;    // 68

    // Shared arena, aliased: [As | Bs] during mainloop, Cs for epilogue.
    __shared__ __align__(16) float smem[BM * LDC];          // 34816 B
    float (*As)[LDA] = reinterpret_cast<float(*)[LDA]>(smem);
    float (*Bs)[LDB] = reinterpret_cast<float(*)[LDB]>(smem + BM * LDA);
    float* Cs = smem;

    const int tid = threadIdx.x;
    const int wid = tid >> 5;
    const int warp_m = wid & 3;
    const int warp_n = wid >> 2;

    const int m0 = blockIdx.x * BM;
    const int n0 = blockIdx.y * BN;

    const float* A = Aglob;
    const float* B = Wall;
    if (MODE == 0) {
        A = (layer == 1) ? g_x : g_h;
        B = Wall + (size_t)blockIdx.z * K * FEAT;
    }

    float4 pa[4], pb[2];

    auto load_a = [&](int k0) {
#pragma unroll
        for (int i = 0; i < 4; i++) {
            const int f = tid + i * 256;
            const int r = f >> 3, kq = (f & 7) * 4;
            const int grow = m0 + r, gk = k0 + kq;
            pa[i] = (grow < M && gk < K)
                  ? *(const float4*)&A[(size_t)grow * K + gk]
                  : make_float4(0.f, 0.f, 0.f, 0.f);
        }
    };
    auto load_b = [&](int k0) {
        if (MODE == 0) {
#pragma unroll
            for (int i = 0; i < 2; i++) {
                const int f = tid + i * 256;
                const int kk = f >> 4, cb = (f & 15) * 4;
                const int gk = k0 + kk;
                pb[i] = (gk < K)
                      ? *(const float4*)&B[(size_t)gk * FEAT + n0 + cb]
                      : make_float4(0.f, 0.f, 0.f, 0.f);
            }
        } else {
#pragma unroll
            for (int i = 0; i < 2; i++) {
                const int f = tid + i * 256;
                const int n = f >> 3, kq = (f & 7) * 4;
                const int gk = k0 + kq;
                pb[i] = (gk < K)
                      ? *(const float4*)&B[(size_t)(n0 + n) * K + gk]
                      : make_float4(0.f, 0.f, 0.f, 0.f);
            }
        }
    };
    auto store_smem = [&]() {
#pragma unroll
        for (int i = 0; i < 4; i++) {
            const int f = tid + i * 256;
            const int r = f >> 3, kq = (f & 7) * 4;
            float4 v = pa[i];
            v.x = wmma::__float_to_tf32(v.x);
            v.y = wmma::__float_to_tf32(v.y);
            v.z = wmma::__float_to_tf32(v.z);
            v.w = wmma::__float_to_tf32(v.w);
            *(float4*)&As[r][kq] = v;
        }
        if (MODE == 0) {
#pragma unroll
            for (int i = 0; i < 2; i++) {
                const int f = tid + i * 256;
                const int kk = f >> 4, cb = (f & 15) * 4;
                float4 v = pb[i];
                v.x = wmma::__float_to_tf32(v.x);
                v.y = wmma::__float_to_tf32(v.y);
                v.z = wmma::__float_to_tf32(v.z);
                v.w = wmma::__float_to_tf32(v.w);
                *(float4*)&Bs[kk][cb] = v;
            }
        } else {
#pragma unroll
            for (int i = 0; i < 2; i++) {
                const int f = tid + i * 256;
                const int n = f >> 3, kq = (f & 7) * 4;
                const float4 v = pb[i];
                Bs[kq + 0][n] = wmma::__float_to_tf32(v.x);
                Bs[kq + 1][n] = wmma::__float_to_tf32(v.y);
                Bs[kq + 2][n] = wmma::__float_to_tf32(v.z);
                Bs[kq + 3][n] = wmma::__float_to_tf32(v.w);
            }
        }
    };

    wmma::fragment<wmma::accumulator, 16, 16, 8, float> cf[2][2];
#pragma unroll
    for (int i = 0; i < 2; i++)
#pragma unroll
        for (int j = 0; j < 2; j++) wmma::fill_fragment(cf[i][j], 0.f);

    load_a(0);
    load_b(0);

    for (int k0 = 0; k0 < K; k0 += BK) {
        __syncthreads();          // previous tile's reads done
        store_smem();
        __syncthreads();
        if (k0 + BK < K) {        // prefetch next tile while mma runs
            load_a(k0 + BK);
            load_b(k0 + BK);
        }
#pragma unroll
        for (int ks = 0; ks < 4; ks++) {
            wmma::fragment<wmma::matrix_a, 16, 16, 8, wmma::precision::tf32,
                           wmma::row_major> af[2];
            wmma::fragment<wmma::matrix_b, 16, 16, 8, wmma::precision::tf32,
                           wmma::row_major> bf[2];
#pragma unroll
            for (int i = 0; i < 2; i++)
                wmma::load_matrix_sync(af[i], &As[warp_m * 32 + i * 16][ks * 8], LDA);
#pragma unroll
            for (int j = 0; j < 2; j++)
                wmma::load_matrix_sync(bf[j], &Bs[ks * 8][warp_n * 32 + j * 16], LDB);
#pragma unroll
            for (int i = 0; i < 2; i++)
#pragma unroll
                for (int j = 0; j < 2; j++)
                    wmma::mma_sync(cf[i][j], af[i], bf[j], cf[i][j]);
        }
    }

    // ---- epilogue ----
    if (MODE == 0 && m0 + BM <= M) {
        // interior block: store accumulators straight to global
        float* C = g_xw + (size_t)blockIdx.z * NNODES * FEAT;
#pragma unroll
        for (int i = 0; i < 2; i++)
#pragma unroll
            for (int j = 0; j < 2; j++)
                wmma::store_matrix_sync(
                    &C[(size_t)(m0 + warp_m * 32 + i * 16) * FEAT +
                       n0 + warp_n * 32 + j * 16],
                    cf[i][j], FEAT, wmma::mem_row_major);
        return;
    }

    // boundary block (and all MODE-1 blocks): stage through shared
    __syncthreads();
#pragma unroll
    for (int i = 0; i < 2; i++)
#pragma unroll
        for (int j = 0; j < 2; j++)
            wmma::store_matrix_sync(&Cs[(warp_m * 32 + i * 16) * LDC +
                                        warp_n * 32 + j * 16],
                                    cf[i][j], LDC, wmma::mem_row_major);
    __syncthreads();

#pragma unroll
    for (int i = 0; i < 32; i++) {
        const int idx = tid + i * 256;
        const int r = idx >> 6, c = idx & 63;
        const int grow = m0 + r;
        if (grow >= M) continue;
        const float acc = Cs[r * LDC + c];
        if (MODE == 1) {
            float v = acc + bias[n0 + c];
            g_x[(size_t)(row_off + grow) * PROJ + n0 + c] = v > 0.f ? v : 0.f;
        } else {
            float* C = g_xw + (size_t)blockIdx.z * NNODES * FEAT;
            C[(size_t)grow * FEAT + n0 + c] = acc;
        }
    }
}

// ---------------------------------------------------------------------------
// qn/kn: per (relation,node) row of g_xw, dot with q[:,h] and k[:,h].
// ---------------------------------------------------------------------------
template <int H>
__global__ void qk_kernel(const float* __restrict__ q,
                          const float* __restrict__ k,
                          int nrows) {
    const int wid  = (blockIdx.x * blockDim.x + threadIdx.x) >> 5;
    const int lane = threadIdx.x & 31;
    if (wid >= nrows) return;
    const float4 v = *(const float4*)&g_xw[(size_t)wid * FEAT + lane * 4];
    const int o0 = lane * 4;
#pragma unroll
    for (int h = 0; h < H; h++) {
        float qa = v.x * q[(o0 + 0) * H + h] + v.y * q[(o0 + 1) * H + h] +
                   v.z * q[(o0 + 2) * H + h] + v.w * q[(o0 + 3) * H + h];
        float ka = v.x * k[(o0 + 0) * H + h] + v.y * k[(o0 + 1) * H + h] +
                   v.z * k[(o0 + 2) * H + h] + v.w * k[(o0 + 3) * H + h];
#pragma unroll
        for (int off = 16; off > 0; off >>= 1) {
            qa += __shfl_down_sync(0xffffffffu, qa, off);
            ka += __shfl_down_sync(0xffffffffu, ka, off);
        }
        if (lane == 0) {
            g_qn[(size_t)wid * H + h] = qa;
            g_kn[(size_t)wid * H + h] = ka;
        }
    }
}

// ---------------------------------------------------------------------------
// Reset m/s/agg each layer.
// ---------------------------------------------------------------------------
__global__ void init_kernel() {
    const int i = blockIdx.x * blockDim.x + threadIdx.x;
    if (i < NNODES * HEADS1) {
        g_m[i] = -INFINITY;
        g_s[i] = 0.f;
    }
    if (i < NNODES * FEAT) g_agg[i] = 0.f;
}

// ---------------------------------------------------------------------------
// Pass A: per-edge logits + segment max (atomicMax).
// ---------------------------------------------------------------------------
template <int H>
__global__ void edge_max(const int* __restrict__ src,
                         const int* __restrict__ dst,
                         const int* __restrict__ et,
                         int E, int dst_limit) {
    const int e = blockIdx.x * blockDim.x + threadIdx.x;
    if (e >= E) return;
    const int d = dst[e];
    if (d >= dst_limit) return;
    const int s = src[e];
    const int t = et[e];
    if (H == 4) {
        const float4 qv = *(const float4*)&g_qn[((size_t)t * NNODES + d) * 4];
        const float4 kv = *(const float4*)&g_kn[((size_t)t * NNODES + s) * 4];
        float al[4] = {qv.x + kv.x, qv.y + kv.y, qv.z + kv.z, qv.w + kv.w};
#pragma unroll
        for (int h = 0; h < 4; h++) {
            al[h] = al[h] > 0.f ? al[h] : SLOPE * al[h];
            atomicMaxFloat(&g_m[d * 4 + h], al[h]);
        }
        *(float4*)&g_alpha[(size_t)e * 4] =
            make_float4(al[0], al[1], al[2], al[3]);
    } else {
        float al = g_qn[(size_t)t * NNODES + d] + g_kn[(size_t)t * NNODES + s];
        al = al > 0.f ? al : SLOPE * al;
        g_alpha[e] = al;
        atomicMaxFloat(&g_m[d], al);
    }
}

// ---------------------------------------------------------------------------
// Pass B: a = exp(alpha - m[dst]); s[dst] += a; agg[dst] += a * xw[etype,src].
// One warp per edge; vectorized red.global.add.v4.f32 scatter (sm_90+).
// ---------------------------------------------------------------------------
template <int H>
__global__ void edge_scatter(const int* __restrict__ src,
                             const int* __restrict__ dst,
                             const int* __restrict__ et,
                             int E, int dst_limit) {
    const int e = (blockIdx.x * blockDim.x + threadIdx.x) >> 5;
    const int lane = threadIdx.x & 31;
    if (e >= E) return;
    const int d = dst[e];
    if (d >= dst_limit) return;
    const int s = src[e];
    const int t = et[e];
    const int h = (H == 1) ? 0 : (lane >> 3);
    const float a = expf(g_alpha[(size_t)e * H + h] - g_m[d * H + h]);
    if (((H == 1) && lane == 0) || ((H == 4) && (lane & 7) == 0))
        atomicAdd(&g_s[d * H + h], a);
    const float4 v = *(const float4*)&g_xw[((size_t)t * NNODES + s) * FEAT + lane * 4];
    red_add_v4(&g_agg[(size_t)d * FEAT + lane * 4],
               a * v.x, a * v.y, a * v.z, a * v.w);
}

// ---------------------------------------------------------------------------
// Normalize + bias + relu -> g_h [nn, FEAT]
// ---------------------------------------------------------------------------
template <int H>
__global__ void normalize_kernel(const float* __restrict__ bias, int nn) {
    const int i = blockIdx.x * blockDim.x + threadIdx.x;
    if (i >= nn * FEAT) return;
    const int n = i >> 7;
    const int o = i & 127;
    const int h = (H == 1) ? 0 : (o >> 5);
    float v = g_agg[i] / (g_s[n * H + h] + 1e-16f) + bias[o];
    g_h[i] = v > 0.f ? v : 0.f;
}

// ---------------------------------------------------------------------------
// Final classifier: out[n,l] = g_h[n,:] . Wl[l,:] + bl[l]  for n < N0.
// ---------------------------------------------------------------------------
__global__ void final_kernel(const float* __restrict__ Wl,
                             const float* __restrict__ bl,
                             float* __restrict__ out) {
    const int n = (blockIdx.x * blockDim.x + threadIdx.x) >> 5;
    const int lane = threadIdx.x & 31;
    if (n >= N0) return;
    const float4 v = *(const float4*)&g_h[(size_t)n * FEAT + lane * 4];
#pragma unroll
    for (int l = 0; l < LAB; l++) {
        const float4 w = *(const float4*)&Wl[l * FEAT + lane * 4];
        float p = v.x * w.x + v.y * w.y + v.z * w.z + v.w * w.w;
#pragma unroll
        for (int off = 16; off > 0; off >>= 1)
            p += __shfl_down_sync(0xffffffffu, p, off);
        if (lane == 0) out[n * LAB + l] = p + bl[l];
    }
}

// ---------------------------------------------------------------------------
// Launcher: ONLY kernel launches.
// ---------------------------------------------------------------------------
extern "C" void kernel_launch(void* const* d_in, const int* in_sizes, int n_in,
                              void* d_out, int out_size) {
    const float* x0  = (const float*)d_in[0];
    const float* x1  = (const float*)d_in[1];
    const float* x2  = (const float*)d_in[2];
    const int*   ei  = (const int*)  d_in[3];
    const int*   et  = (const int*)  d_in[4];
    const float* Wp0 = (const float*)d_in[5];
    const float* bp0 = (const float*)d_in[6];
    const float* Wp1 = (const float*)d_in[7];
    const float* bp1 = (const float*)d_in[8];
    const float* Wp2 = (const float*)d_in[9];
    const float* bp2 = (const float*)d_in[10];
    const float* W1  = (const float*)d_in[11];
    const float* q1  = (const float*)d_in[12];
    const float* k1  = (const float*)d_in[13];
    const float* b1  = (const float*)d_in[14];
    const float* W2  = (const float*)d_in[15];
    const float* q2  = (const float*)d_in[16];
    const float* k2  = (const float*)d_in[17];
    const float* b2  = (const float*)d_in[18];
    const float* Wl  = (const float*)d_in[19];
    const float* bl  = (const float*)d_in[20];
    float* out = (float*)d_out;

    const int E = in_sizes[4];          // 400000
    const int* srcp = ei;
    const int* dstp = ei + E;

    const int TPB = 256;

    // --- projections ---
    {
        dim3 g((N0 + 127) / 128, PROJ / 64);
        gemm_tf32<1><<<g, TPB>>>(x0, Wp0, bp0, N0, 2000, 0,      0);
        gemm_tf32<1><<<g, TPB>>>(x1, Wp1, bp1, N0, 1500, N0,     0);
        gemm_tf32<1><<<g, TPB>>>(x2, Wp2, bp2, N0, 1000, 2 * N0, 0);
    }

    const int nrows = RNUM * NNODES;
    const int qk_blocks = (nrows * 32 + TPB - 1) / TPB;
    const int init_blocks = (NNODES * FEAT + TPB - 1) / TPB;
    const int ea_blocks = (E + TPB - 1) / TPB;
    const int eb_blocks = (E * 32 + TPB - 1) / TPB;

    // --- layer 1 ---
    {
        dim3 g((NNODES + 127) / 128, FEAT / 64, RNUM);
        gemm_tf32<0><<<g, TPB>>>(nullptr, W1, nullptr, NNODES, PROJ, 0, 1);
    }
    qk_kernel<HEADS1><<<qk_blocks, TPB>>>(q1, k1, nrows);
    init_kernel<<<init_blocks, TPB>>>();
    edge_max<HEADS1><<<ea_blocks, TPB>>>(srcp, dstp, et, E, NNODES);
    edge_scatter<HEADS1><<<eb_blocks, TPB>>>(srcp, dstp, et, E, NNODES);
    normalize_kernel<HEADS1><<<(NNODES * FEAT + TPB - 1) / TPB, TPB>>>(b1, NNODES);

    // --- layer 2 (only dst < N0 matter for the final classifier) ---
    {
        dim3 g((NNODES + 127) / 128, FEAT / 64, RNUM);
        gemm_tf32<0><<<g, TPB>>>(nullptr, W2, nullptr, NNODES, FEAT, 0, 2);
    }
    qk_kernel<1><<<qk_blocks, TPB>>>(q2, k2, nrows);
    init_kernel<<<init_blocks, TPB>>>();
    edge_max<1><<<ea_blocks, TPB>>>(srcp, dstp, et, E, N0);
    edge_scatter<1><<<eb_blocks, TPB>>>(srcp, dstp, et, E, N0);
    normalize_kernel<1><<<(N0 * FEAT + TPB - 1) / TPB, TPB>>>(b2, N0);

    // --- classifier ---
    final_kernel<<<(N0 * 32 + TPB - 1) / TPB, TPB>>>(Wl, bl, out);
}

// round 8
// speedup vs baseline: 1.5789x; 1.0610x over previous
#include <cuda_runtime.h>
#include <math.h>
#include <mma.h>

using namespace nvcuda;

// ---------------------------------------------------------------------------
// Problem constants
// ---------------------------------------------------------------------------
namespace {
constexpr int N0     = 10000;
constexpr int NNODES = 30000;
constexpr int PROJ   = 256;
constexpr int RNUM   = 6;
constexpr int HEADS1 = 4;
constexpr int FEAT   = 128;
constexpr int LAB    = 5;
constexpr int EMAX   = 400000;
constexpr float SLOPE = 0.2f;
constexpr int SCAN_BLK = 512;
constexpr int SCAN_NB  = (NNODES + SCAN_BLK - 1) / SCAN_BLK;   // 59
}

// ---------------------------------------------------------------------------
// Scratch (static device globals; no allocation anywhere).
// ---------------------------------------------------------------------------
__device__ float g_x    [(size_t)NNODES * PROJ];
__device__ float g_xw   [(size_t)RNUM * NNODES * FEAT];
__device__ float g_h    [(size_t)NNODES * FEAT];
__device__ float g_qn   [(size_t)RNUM * NNODES * HEADS1];
__device__ float g_kn   [(size_t)RNUM * NNODES * HEADS1];
__device__ float g_alpha[(size_t)EMAX * HEADS1];
// CSR scratch
__device__ int g_cnt    [NNODES];
__device__ int g_rowptr [NNODES + 1];
__device__ int g_bsum   [64];
__device__ int g_boff   [64];
__device__ int g_cursor [NNODES];
__device__ int g_perm   [EMAX];
__device__ int g_packed [EMAX];     // src | (etype << 17)

// ---------------------------------------------------------------------------
// TF32 tensor-core GEMM (unchanged from R7 — proven at 1549 us).
// MODE 0 (rel):  A = g_x (layer==1) or g_h (layer==2); B = Wall + z*K*FEAT.
// MODE 1 (proj): A = Aglob; B = Wall [256,K] used transposed; bias+ReLU.
// ---------------------------------------------------------------------------
template <int MODE>
__global__ void __launch_bounds__(256, 2)
gemm_tf32(const float* __restrict__ Aglob,
          const float* __restrict__ Wall,
          const float* __restrict__ bias,
          int M, int K, int row_off, int layer) {
    constexpr int BM = 128, BN = 64, BK = 32;
    constexpr int LDA = BK + 4;
    constexpr int LDB = BN + 4;
    constexpr int LDC = BN + 4;

    __shared__ __align__(16) float smem[BM * LDC];
    float (*As)[LDA] = reinterpret_cast<float(*)[LDA]>(smem);
    float (*Bs)[LDB] = reinterpret_cast<float(*)[LDB]>(smem + BM * LDA);
    float* Cs = smem;

    const int tid = threadIdx.x;
    const int wid = tid >> 5;
    const int warp_m = wid & 3;
    const int warp_n = wid >> 2;

    const int m0 = blockIdx.x * BM;
    const int n0 = blockIdx.y * BN;

    const float* A = Aglob;
    const float* B = Wall;
    if (MODE == 0) {
        A = (layer == 1) ? g_x : g_h;
        B = Wall + (size_t)blockIdx.z * K * FEAT;
    }

    float4 pa[4], pb[2];

    auto load_a = [&](int k0) {
#pragma unroll
        for (int i = 0; i < 4; i++) {
            const int f = tid + i * 256;
            const int r = f >> 3, kq = (f & 7) * 4;
            const int grow = m0 + r, gk = k0 + kq;
            pa[i] = (grow < M && gk < K)
                  ? *(const float4*)&A[(size_t)grow * K + gk]
                  : make_float4(0.f, 0.f, 0.f, 0.f);
        }
    };
    auto load_b = [&](int k0) {
        if (MODE == 0) {
#pragma unroll
            for (int i = 0; i < 2; i++) {
                const int f = tid + i * 256;
                const int kk = f >> 4, cb = (f & 15) * 4;
                const int gk = k0 + kk;
                pb[i] = (gk < K)
                      ? *(const float4*)&B[(size_t)gk * FEAT + n0 + cb]
                      : make_float4(0.f, 0.f, 0.f, 0.f);
            }
        } else {
#pragma unroll
            for (int i = 0; i < 2; i++) {
                const int f = tid + i * 256;
                const int n = f >> 3, kq = (f & 7) * 4;
                const int gk = k0 + kq;
                pb[i] = (gk < K)
                      ? *(const float4*)&B[(size_t)(n0 + n) * K + gk]
                      : make_float4(0.f, 0.f, 0.f, 0.f);
            }
        }
    };
    auto store_smem = [&]() {
#pragma unroll
        for (int i = 0; i < 4; i++) {
            const int f = tid + i * 256;
            const int r = f >> 3, kq = (f & 7) * 4;
            float4 v = pa[i];
            v.x = wmma::__float_to_tf32(v.x);
            v.y = wmma::__float_to_tf32(v.y);
            v.z = wmma::__float_to_tf32(v.z);
            v.w = wmma::__float_to_tf32(v.w);
            *(float4*)&As[r][kq] = v;
        }
        if (MODE == 0) {
#pragma unroll
            for (int i = 0; i < 2; i++) {
                const int f = tid + i * 256;
                const int kk = f >> 4, cb = (f & 15) * 4;
                float4 v = pb[i];
                v.x = wmma::__float_to_tf32(v.x);
                v.y = wmma::__float_to_tf32(v.y);
                v.z = wmma::__float_to_tf32(v.z);
                v.w = wmma::__float_to_tf32(v.w);
                *(float4*)&Bs[kk][cb] = v;
            }
        } else {
#pragma unroll
            for (int i = 0; i < 2; i++) {
                const int f = tid + i * 256;
                const int n = f >> 3, kq = (f & 7) * 4;
                const float4 v = pb[i];
                Bs[kq + 0][n] = wmma::__float_to_tf32(v.x);
                Bs[kq + 1][n] = wmma::__float_to_tf32(v.y);
                Bs[kq + 2][n] = wmma::__float_to_tf32(v.z);
                Bs[kq + 3][n] = wmma::__float_to_tf32(v.w);
            }
        }
    };

    wmma::fragment<wmma::accumulator, 16, 16, 8, float> cf[2][2];
#pragma unroll
    for (int i = 0; i < 2; i++)
#pragma unroll
        for (int j = 0; j < 2; j++) wmma::fill_fragment(cf[i][j], 0.f);

    load_a(0);
    load_b(0);

    for (int k0 = 0; k0 < K; k0 += BK) {
        __syncthreads();
        store_smem();
        __syncthreads();
        if (k0 + BK < K) {
            load_a(k0 + BK);
            load_b(k0 + BK);
        }
#pragma unroll
        for (int ks = 0; ks < 4; ks++) {
            wmma::fragment<wmma::matrix_a, 16, 16, 8, wmma::precision::tf32,
                           wmma::row_major> af[2];
            wmma::fragment<wmma::matrix_b, 16, 16, 8, wmma::precision::tf32,
                           wmma::row_major> bf[2];
#pragma unroll
            for (int i = 0; i < 2; i++)
                wmma::load_matrix_sync(af[i], &As[warp_m * 32 + i * 16][ks * 8], LDA);
#pragma unroll
            for (int j = 0; j < 2; j++)
                wmma::load_matrix_sync(bf[j], &Bs[ks * 8][warp_n * 32 + j * 16], LDB);
#pragma unroll
            for (int i = 0; i < 2; i++)
#pragma unroll
                for (int j = 0; j < 2; j++)
                    wmma::mma_sync(cf[i][j], af[i], bf[j], cf[i][j]);
        }
    }

    if (MODE == 0 && m0 + BM <= M) {
        float* C = g_xw + (size_t)blockIdx.z * NNODES * FEAT;
#pragma unroll
        for (int i = 0; i < 2; i++)
#pragma unroll
            for (int j = 0; j < 2; j++)
                wmma::store_matrix_sync(
                    &C[(size_t)(m0 + warp_m * 32 + i * 16) * FEAT +
                       n0 + warp_n * 32 + j * 16],
                    cf[i][j], FEAT, wmma::mem_row_major);
        return;
    }

    __syncthreads();
#pragma unroll
    for (int i = 0; i < 2; i++)
#pragma unroll
        for (int j = 0; j < 2; j++)
            wmma::store_matrix_sync(&Cs[(warp_m * 32 + i * 16) * LDC +
                                        warp_n * 32 + j * 16],
                                    cf[i][j], LDC, wmma::mem_row_major);
    __syncthreads();

#pragma unroll
    for (int i = 0; i < 32; i++) {
        const int idx = tid + i * 256;
        const int r = idx >> 6, c = idx & 63;
        const int grow = m0 + r;
        if (grow >= M) continue;
        const float acc = Cs[r * LDC + c];
        if (MODE == 1) {
            float v = acc + bias[n0 + c];
            g_x[(size_t)(row_off + grow) * PROJ + n0 + c] = v > 0.f ? v : 0.f;
        } else {
            float* C = g_xw + (size_t)blockIdx.z * NNODES * FEAT;
            C[(size_t)grow * FEAT + n0 + c] = acc;
        }
    }
}

// ---------------------------------------------------------------------------
// qn/kn precompute (unchanged).
// ---------------------------------------------------------------------------
template <int H>
__global__ void qk_kernel(const float* __restrict__ q,
                          const float* __restrict__ k,
                          int nrows) {
    const int wid  = (blockIdx.x * blockDim.x + threadIdx.x) >> 5;
    const int lane = threadIdx.x & 31;
    if (wid >= nrows) return;
    const float4 v = *(const float4*)&g_xw[(size_t)wid * FEAT + lane * 4];
    const int o0 = lane * 4;
#pragma unroll
    for (int h = 0; h < H; h++) {
        float qa = v.x * q[(o0 + 0) * H + h] + v.y * q[(o0 + 1) * H + h] +
                   v.z * q[(o0 + 2) * H + h] + v.w * q[(o0 + 3) * H + h];
        float ka = v.x * k[(o0 + 0) * H + h] + v.y * k[(o0 + 1) * H + h] +
                   v.z * k[(o0 + 2) * H + h] + v.w * k[(o0 + 3) * H + h];
#pragma unroll
        for (int off = 16; off > 0; off >>= 1) {
            qa += __shfl_down_sync(0xffffffffu, qa, off);
            ka += __shfl_down_sync(0xffffffffu, ka, off);
        }
        if (lane == 0) {
            g_qn[(size_t)wid * H + h] = qa;
            g_kn[(size_t)wid * H + h] = ka;
        }
    }
}

// ---------------------------------------------------------------------------
// CSR build: histogram -> block scan -> add offsets -> permutation fill.
// ---------------------------------------------------------------------------
__global__ void csr_zero() {
    const int i = blockIdx.x * blockDim.x + threadIdx.x;
    if (i < NNODES) g_cnt[i] = 0;
}
__global__ void csr_hist(const int* __restrict__ dst, int E) {
    const int e = blockIdx.x * blockDim.x + threadIdx.x;
    if (e < E) atomicAdd(&g_cnt[dst[e]], 1);
}
__global__ void csr_scan_block() {
    __shared__ int sm[SCAN_BLK];
    const int tid = threadIdx.x;
    const int i = blockIdx.x * SCAN_BLK + tid;
    sm[tid] = (i < NNODES) ? g_cnt[i] : 0;
    __syncthreads();
    for (int off = 1; off < SCAN_BLK; off <<= 1) {
        int t = (tid >= off) ? sm[tid - off] : 0;
        __syncthreads();
        sm[tid] += t;
        __syncthreads();
    }
    if (i < NNODES) g_rowptr[i + 1] = sm[tid];
    if (tid == SCAN_BLK - 1) g_bsum[blockIdx.x] = sm[tid];
}
__global__ void csr_scan_sums() {
    __shared__ int sm[64];
    const int tid = threadIdx.x;                 // 64 threads
    const int v = (tid < SCAN_NB) ? g_bsum[tid] : 0;
    sm[tid] = v;
    __syncthreads();
    for (int off = 1; off < 64; off <<= 1) {
        int t = (tid >= off) ? sm[tid - off] : 0;
        __syncthreads();
        sm[tid] += t;
        __syncthreads();
    }
    if (tid < SCAN_NB) g_boff[tid] = sm[tid] - v;   // exclusive
}
__global__ void csr_scan_add() {
    const int i = blockIdx.x * blockDim.x + threadIdx.x;
    if (i < NNODES) g_rowptr[i + 1] += g_boff[i / SCAN_BLK];
    if (i == 0) g_rowptr[0] = 0;
}
__global__ void csr_cursor() {
    const int i = blockIdx.x * blockDim.x + threadIdx.x;
    if (i < NNODES) g_cursor[i] = g_rowptr[i];
}
__global__ void csr_fill(const int* __restrict__ dst, int E) {
    const int e = blockIdx.x * blockDim.x + threadIdx.x;
    if (e >= E) return;
    const int pos = atomicAdd(&g_cursor[dst[e]], 1);
    g_perm[pos] = e;
}

// ---------------------------------------------------------------------------
// Fused attention-aggregation: one warp per destination node.
// Replaces init/edge_max/edge_scatter/normalize. No float atomics.
//   pass1: logits (leaky-relu) lane-parallel over edges, warp max
//   pass2: exp + warp sum (stored back to g_alpha)
//   pass3: sequential edge walk, lane = 4 features, gather+fma
//   epilogue: /(s+1e-16) + bias, ReLU -> g_h
// ---------------------------------------------------------------------------
template <int H>
__global__ void agg_kernel(const int* __restrict__ src,
                           const int* __restrict__ et,
                           const float* __restrict__ bias, int nn) {
    const int d = (blockIdx.x * blockDim.x + threadIdx.x) >> 5;
    const int lane = threadIdx.x & 31;
    if (d >= nn) return;
    const int beg = g_rowptr[d];
    const int end = g_rowptr[d + 1];

    float m0 = -INFINITY, m1 = -INFINITY, m2 = -INFINITY, m3 = -INFINITY;

    // ---- pass 1: logits + max ----
    for (int j = beg + lane; j < end; j += 32) {
        const int e = g_perm[j];
        const int s = src[e];
        const int t = et[e];
        g_packed[j] = s | (t << 17);
        if (H == 4) {
            const float4 qv = *(const float4*)&g_qn[((size_t)t * NNODES + d) * 4];
            const float4 kv = *(const float4*)&g_kn[((size_t)t * NNODES + s) * 4];
            float a0 = qv.x + kv.x, a1 = qv.y + kv.y;
            float a2 = qv.z + kv.z, a3 = qv.w + kv.w;
            a0 = a0 > 0.f ? a0 : SLOPE * a0;
            a1 = a1 > 0.f ? a1 : SLOPE * a1;
            a2 = a2 > 0.f ? a2 : SLOPE * a2;
            a3 = a3 > 0.f ? a3 : SLOPE * a3;
            *(float4*)&g_alpha[(size_t)j * 4] = make_float4(a0, a1, a2, a3);
            m0 = fmaxf(m0, a0); m1 = fmaxf(m1, a1);
            m2 = fmaxf(m2, a2); m3 = fmaxf(m3, a3);
        } else {
            float a = g_qn[(size_t)t * NNODES + d] + g_kn[(size_t)t * NNODES + s];
            a = a > 0.f ? a : SLOPE * a;
            g_alpha[j] = a;
            m0 = fmaxf(m0, a);
        }
    }
#pragma unroll
    for (int off = 16; off > 0; off >>= 1) {
        m0 = fmaxf(m0, __shfl_xor_sync(0xffffffffu, m0, off));
        if (H == 4) {
            m1 = fmaxf(m1, __shfl_xor_sync(0xffffffffu, m1, off));
            m2 = fmaxf(m2, __shfl_xor_sync(0xffffffffu, m2, off));
            m3 = fmaxf(m3, __shfl_xor_sync(0xffffffffu, m3, off));
        }
    }

    // ---- pass 2: exp + sum ----
    float s0 = 0.f, s1 = 0.f, s2 = 0.f, s3 = 0.f;
    for (int j = beg + lane; j < end; j += 32) {
        if (H == 4) {
            float4 al = *(const float4*)&g_alpha[(size_t)j * 4];
            al.x = expf(al.x - m0); al.y = expf(al.y - m1);
            al.z = expf(al.z - m2); al.w = expf(al.w - m3);
            *(float4*)&g_alpha[(size_t)j * 4] = al;
            s0 += al.x; s1 += al.y; s2 += al.z; s3 += al.w;
        } else {
            const float a = expf(g_alpha[j] - m0);
            g_alpha[j] = a;
            s0 += a;
        }
    }
#pragma unroll
    for (int off = 16; off > 0; off >>= 1) {
        s0 += __shfl_xor_sync(0xffffffffu, s0, off);
        if (H == 4) {
            s1 += __shfl_xor_sync(0xffffffffu, s1, off);
            s2 += __shfl_xor_sync(0xffffffffu, s2, off);
            s3 += __shfl_xor_sync(0xffffffffu, s3, off);
        }
    }
    __syncwarp();
    __threadfence_block();   // pass2/1 stores visible to cross-lane pass3 loads

    // ---- pass 3: feature accumulation (lane = 4 feats) ----
    const int h = (H == 1) ? 0 : (lane >> 3);
    float sh = s0;
    if (H == 4) sh = (h & 2) ? ((h & 1) ? s3 : s2) : ((h & 1) ? s1 : s0);

    float4 acc = make_float4(0.f, 0.f, 0.f, 0.f);
    for (int j = beg; j < end; j++) {
        const int pk = g_packed[j];
        const int s_ = pk & 0x1FFFF;
        const int t_ = pk >> 17;
        const float a = g_alpha[(size_t)j * H + h];
        const float4 v = *(const float4*)
            &g_xw[((size_t)t_ * NNODES + s_) * FEAT + lane * 4];
        acc.x += a * v.x; acc.y += a * v.y;
        acc.z += a * v.z; acc.w += a * v.w;
    }
    const float inv = 1.f / (sh + 1e-16f);
    const int o = lane * 4;
    float4 r;
    r.x = acc.x * inv + bias[o + 0];
    r.y = acc.y * inv + bias[o + 1];
    r.z = acc.z * inv + bias[o + 2];
    r.w = acc.w * inv + bias[o + 3];
    r.x = r.x > 0.f ? r.x : 0.f;
    r.y = r.y > 0.f ? r.y : 0.f;
    r.z = r.z > 0.f ? r.z : 0.f;
    r.w = r.w > 0.f ? r.w : 0.f;
    *(float4*)&g_h[(size_t)d * FEAT + o] = r;
}

// ---------------------------------------------------------------------------
// Final classifier.
// ---------------------------------------------------------------------------
__global__ void final_kernel(const float* __restrict__ Wl,
                             const float* __restrict__ bl,
                             float* __restrict__ out) {
    const int n = (blockIdx.x * blockDim.x + threadIdx.x) >> 5;
    const int lane = threadIdx.x & 31;
    if (n >= N0) return;
    const float4 v = *(const float4*)&g_h[(size_t)n * FEAT + lane * 4];
#pragma unroll
    for (int l = 0; l < LAB; l++) {
        const float4 w = *(const float4*)&Wl[l * FEAT + lane * 4];
        float p = v.x * w.x + v.y * w.y + v.z * w.z + v.w * w.w;
#pragma unroll
        for (int off = 16; off > 0; off >>= 1)
            p += __shfl_down_sync(0xffffffffu, p, off);
        if (lane == 0) out[n * LAB + l] = p + bl[l];
    }
}

// ---------------------------------------------------------------------------
// Launcher: ONLY kernel launches.
// ---------------------------------------------------------------------------
extern "C" void kernel_launch(void* const* d_in, const int* in_sizes, int n_in,
                              void* d_out, int out_size) {
    const float* x0  = (const float*)d_in[0];
    const float* x1  = (const float*)d_in[1];
    const float* x2  = (const float*)d_in[2];
    const int*   ei  = (const int*)  d_in[3];
    const int*   et  = (const int*)  d_in[4];
    const float* Wp0 = (const float*)d_in[5];
    const float* bp0 = (const float*)d_in[6];
    const float* Wp1 = (const float*)d_in[7];
    const float* bp1 = (const float*)d_in[8];
    const float* Wp2 = (const float*)d_in[9];
    const float* bp2 = (const float*)d_in[10];
    const float* W1  = (const float*)d_in[11];
    const float* q1  = (const float*)d_in[12];
    const float* k1  = (const float*)d_in[13];
    const float* b1  = (const float*)d_in[14];
    const float* W2  = (const float*)d_in[15];
    const float* q2  = (const float*)d_in[16];
    const float* k2  = (const float*)d_in[17];
    const float* b2  = (const float*)d_in[18];
    const float* Wl  = (const float*)d_in[19];
    const float* bl  = (const float*)d_in[20];
    float* out = (float*)d_out;

    const int E = in_sizes[4];          // 400000
    const int* srcp = ei;
    const int* dstp = ei + E;

    const int TPB = 256;

    // --- projections ---
    {
        dim3 g((N0 + 127) / 128, PROJ / 64);
        gemm_tf32<1><<<g, TPB>>>(x0, Wp0, bp0, N0, 2000, 0,      0);
        gemm_tf32<1><<<g, TPB>>>(x1, Wp1, bp1, N0, 1500, N0,     0);
        gemm_tf32<1><<<g, TPB>>>(x2, Wp2, bp2, N0, 1000, 2 * N0, 0);
    }

    // --- CSR build (edges constant across both layers) ---
    {
        const int nb_n = (NNODES + TPB - 1) / TPB;
        const int nb_e = (E + TPB - 1) / TPB;
        csr_zero<<<nb_n, TPB>>>();
        csr_hist<<<nb_e, TPB>>>(dstp, E);
        csr_scan_block<<<SCAN_NB, SCAN_BLK>>>();
        csr_scan_sums<<<1, 64>>>();
        csr_scan_add<<<nb_n, TPB>>>();
        csr_cursor<<<nb_n, TPB>>>();
        csr_fill<<<nb_e, TPB>>>(dstp, E);
    }

    const int nrows = RNUM * NNODES;
    const int qk_blocks = (nrows * 32 + TPB - 1) / TPB;

    // --- layer 1 ---
    {
        dim3 g((NNODES + 127) / 128, FEAT / 64, RNUM);
        gemm_tf32<0><<<g, TPB>>>(nullptr, W1, nullptr, NNODES, PROJ, 0, 1);
    }
    qk_kernel<HEADS1><<<qk_blocks, TPB>>>(q1, k1, nrows);
    agg_kernel<HEADS1><<<(NNODES * 32 + TPB - 1) / TPB, TPB>>>(srcp, et, b1, NNODES);

    // --- layer 2 (only dst < N0 matter for the final classifier) ---
    {
        dim3 g((NNODES + 127) / 128, FEAT / 64, RNUM);
        gemm_tf32<0><<<g, TPB>>>(nullptr, W2, nullptr, NNODES, FEAT, 0, 2);
    }
    qk_kernel<1><<<qk_blocks, TPB>>>(q2, k2, nrows);
    agg_kernel<1><<<(N0 * 32 + TPB - 1) / TPB, TPB>>>(srcp, et, b2, N0);

    // --- classifier ---
    final_kernel<<<(N0 * 32 + TPB - 1) / TPB, TPB>>>(Wl, bl, out);
}

// round 9
// speedup vs baseline: 1.9272x; 1.2206x over previous
#include <cuda_runtime.h>
#include <math.h>
#include <mma.h>

using namespace nvcuda;

// ---------------------------------------------------------------------------
// Problem constants
// ---------------------------------------------------------------------------
namespace {
constexpr int N0     = 10000;
constexpr int NNODES = 30000;
constexpr int PROJ   = 256;
constexpr int RNUM   = 6;
constexpr int HEADS1 = 4;
constexpr int FEAT   = 128;
constexpr int LAB    = 5;
constexpr int EMAX   = 400000;
constexpr float SLOPE = 0.2f;
constexpr int SCAN_BLK = 512;
constexpr int SCAN_NB  = (NNODES + SCAN_BLK - 1) / SCAN_BLK;   // 59
}

// ---------------------------------------------------------------------------
// Scratch (static device globals; no allocation anywhere).
// ---------------------------------------------------------------------------
__device__ float g_x    [(size_t)NNODES * PROJ];
__device__ float g_xw   [(size_t)RNUM * NNODES * FEAT];
__device__ float g_h    [(size_t)NNODES * FEAT];
__device__ float g_qn   [(size_t)RNUM * NNODES * HEADS1];
__device__ float g_kn   [(size_t)RNUM * NNODES * HEADS1];
__device__ float g_alpha[(size_t)EMAX * HEADS1];
// CSR scratch
__device__ int g_cnt    [NNODES];
__device__ int g_rowptr [NNODES + 1];
__device__ int g_bsum   [64];
__device__ int g_boff   [64];
__device__ int g_cursor [NNODES];
__device__ int g_perm   [EMAX];
__device__ int g_packed [EMAX];     // src | (etype << 17)

// ---------------------------------------------------------------------------
// TF32 tensor-core GEMM, 128x128 block tile, BK=32, 256 threads (8 warps).
// Warp tile 32x64 = 2x4 wmma m16n16k8 fragments (8 mmas / 6 fragment loads).
//
// MODE 0 (rel):  A = g_x (layer==1) or g_h (layer==2), [M,K0] row-major.
//                B = W0 + blockIdx.z*K0*FEAT, [K0,FEAT] row-major. n0 = 0.
//                C = g_xw + blockIdx.z*NNODES*FEAT, plain store.
// MODE 1 (proj): blockIdx.z = omic z; A = Az [M,Kz]; B = Wz [256,Kz] used
//                transposed; C = g_x rows z*N0.., bias+ReLU epilogue.
// ---------------------------------------------------------------------------
template <int MODE>
__global__ void __launch_bounds__(256, 2)
gemm128(const float* __restrict__ A0, const float* __restrict__ A1,
        const float* __restrict__ A2,
        const float* __restrict__ W0, const float* __restrict__ W1,
        const float* __restrict__ W2,
        const float* __restrict__ bb0, const float* __restrict__ bb1,
        const float* __restrict__ bb2,
        int K0, int K1, int K2, int M, int layer) {
    constexpr int BM = 128, BN = 128, BK = 32;
    constexpr int LDA = BK + 4;    // 36
    constexpr int LDB = BN + 4;    // 132
    constexpr int LDC = BN + 4;    // 132

    // Arena: [As 128x36 | Bs 32x132] = 8832 floats; epilogue reuses 64xLDC=8448.
    __shared__ __align__(16) float smem[BM * LDA + BK * LDB];
    float (*As)[LDA] = reinterpret_cast<float(*)[LDA]>(smem);
    float (*Bs)[LDB] = reinterpret_cast<float(*)[LDB]>(smem + BM * LDA);
    float* Cs = smem;

    const int tid = threadIdx.x;
    const int wid = tid >> 5;
    const int warp_m = wid & 3;      // 32-row slab
    const int warp_n = wid >> 2;     // 64-col slab

    const int m0 = blockIdx.x * BM;
    const int n0 = (MODE == 1) ? blockIdx.y * BN : 0;
    const int z  = blockIdx.z;

    const float* A;
    const float* B;
    const float* bias = nullptr;
    int K, row_off = 0;
    if (MODE == 0) {
        A = (layer == 1) ? g_x : g_h;
        K = K0;
        B = W0 + (size_t)z * K0 * FEAT;
    } else {
        A    = (z == 0) ? A0 : (z == 1) ? A1 : A2;
        B    = (z == 0) ? W0 : (z == 1) ? W1 : W2;
        bias = (z == 0) ? bb0 : (z == 1) ? bb1 : bb2;
        K    = (z == 0) ? K0 : (z == 1) ? K1 : K2;
        row_off = z * N0;
    }

    wmma::fragment<wmma::accumulator, 16, 16, 8, float> cf[2][4];
#pragma unroll
    for (int i = 0; i < 2; i++)
#pragma unroll
        for (int j = 0; j < 4; j++) wmma::fill_fragment(cf[i][j], 0.f);

    for (int k0 = 0; k0 < K; k0 += BK) {
        // ---- A tile: 128x32 = 1024 float4, 4 per thread ----
#pragma unroll
        for (int i = 0; i < 4; i++) {
            const int f = tid + i * 256;
            const int r = f >> 3, kq = (f & 7) * 4;
            const int grow = m0 + r, gk = k0 + kq;
            float4 v = make_float4(0.f, 0.f, 0.f, 0.f);
            if (grow < M && gk < K)
                v = *(const float4*)&A[(size_t)grow * K + gk];
            v.x = wmma::__float_to_tf32(v.x);
            v.y = wmma::__float_to_tf32(v.y);
            v.z = wmma::__float_to_tf32(v.z);
            v.w = wmma::__float_to_tf32(v.w);
            *(float4*)&As[r][kq] = v;
        }
        // ---- B tile: 32x128 = 1024 float4, 4 per thread ----
        if (MODE == 0) {
#pragma unroll
            for (int i = 0; i < 4; i++) {
                const int f = tid + i * 256;
                const int kk = f >> 5, cb = (f & 31) * 4;
                const int gk = k0 + kk;
                float4 v = make_float4(0.f, 0.f, 0.f, 0.f);
                if (gk < K)
                    v = *(const float4*)&B[(size_t)gk * FEAT + cb];
                v.x = wmma::__float_to_tf32(v.x);
                v.y = wmma::__float_to_tf32(v.y);
                v.z = wmma::__float_to_tf32(v.z);
                v.w = wmma::__float_to_tf32(v.w);
                *(float4*)&Bs[kk][cb] = v;
            }
        } else {
            // transpose: Bs[k][n] = W[(n0+n)*K + k0+k]
#pragma unroll
            for (int i = 0; i < 4; i++) {
                const int f = tid + i * 256;
                const int n = f >> 3, kq = (f & 7) * 4;
                const int gk = k0 + kq;
                float4 v = make_float4(0.f, 0.f, 0.f, 0.f);
                if (gk < K)
                    v = *(const float4*)&B[(size_t)(n0 + n) * K + gk];
                Bs[kq + 0][n] = wmma::__float_to_tf32(v.x);
                Bs[kq + 1][n] = wmma::__float_to_tf32(v.y);
                Bs[kq + 2][n] = wmma::__float_to_tf32(v.z);
                Bs[kq + 3][n] = wmma::__float_to_tf32(v.w);
            }
        }
        __syncthreads();

#pragma unroll
        for (int ks = 0; ks < 4; ks++) {
            wmma::fragment<wmma::matrix_a, 16, 16, 8, wmma::precision::tf32,
                           wmma::row_major> af[2];
            wmma::fragment<wmma::matrix_b, 16, 16, 8, wmma::precision::tf32,
                           wmma::row_major> bf[4];
#pragma unroll
            for (int i = 0; i < 2; i++)
                wmma::load_matrix_sync(af[i], &As[warp_m * 32 + i * 16][ks * 8], LDA);
#pragma unroll
            for (int j = 0; j < 4; j++)
                wmma::load_matrix_sync(bf[j], &Bs[ks * 8][warp_n * 64 + j * 16], LDB);
#pragma unroll
            for (int i = 0; i < 2; i++)
#pragma unroll
                for (int j = 0; j < 4; j++)
                    wmma::mma_sync(cf[i][j], af[i], bf[j], cf[i][j]);
        }
        __syncthreads();
    }

    // ---- epilogue ----
    if (MODE == 0 && m0 + BM <= M) {
        float* C = g_xw + (size_t)z * NNODES * FEAT;
#pragma unroll
        for (int i = 0; i < 2; i++)
#pragma unroll
            for (int j = 0; j < 4; j++)
                wmma::store_matrix_sync(
                    &C[(size_t)(m0 + warp_m * 32 + i * 16) * FEAT +
                       warp_n * 64 + j * 16],
                    cf[i][j], FEAT, wmma::mem_row_major);
        return;
    }

    // staged path: two 64-row halves through the smem arena
#pragma unroll
    for (int half = 0; half < 2; half++) {
        __syncthreads();
        if ((warp_m >> 1) == half) {
            const int lm = (warp_m & 1) * 32;
#pragma unroll
            for (int i = 0; i < 2; i++)
#pragma unroll
                for (int j = 0; j < 4; j++)
                    wmma::store_matrix_sync(&Cs[(lm + i * 16) * LDC +
                                                warp_n * 64 + j * 16],
                                            cf[i][j], LDC, wmma::mem_row_major);
        }
        __syncthreads();
#pragma unroll
        for (int i = 0; i < 32; i++) {
            const int idx = tid + i * 256;       // 0..8191
            const int r = idx >> 7, c = idx & 127;
            const int grow = m0 + half * 64 + r;
            if (grow >= M) continue;
            const float acc = Cs[r * LDC + c];
            if (MODE == 1) {
                float v = acc + bias[n0 + c];
                g_x[(size_t)(row_off + grow) * PROJ + n0 + c] = v > 0.f ? v : 0.f;
            } else {
                float* C = g_xw + (size_t)z * NNODES * FEAT;
                C[(size_t)grow * FEAT + c] = acc;
            }
        }
    }
}

// ---------------------------------------------------------------------------
// qn/kn precompute (unchanged).
// ---------------------------------------------------------------------------
template <int H>
__global__ void qk_kernel(const float* __restrict__ q,
                          const float* __restrict__ k,
                          int nrows) {
    const int wid  = (blockIdx.x * blockDim.x + threadIdx.x) >> 5;
    const int lane = threadIdx.x & 31;
    if (wid >= nrows) return;
    const float4 v = *(const float4*)&g_xw[(size_t)wid * FEAT + lane * 4];
    const int o0 = lane * 4;
#pragma unroll
    for (int h = 0; h < H; h++) {
        float qa = v.x * q[(o0 + 0) * H + h] + v.y * q[(o0 + 1) * H + h] +
                   v.z * q[(o0 + 2) * H + h] + v.w * q[(o0 + 3) * H + h];
        float ka = v.x * k[(o0 + 0) * H + h] + v.y * k[(o0 + 1) * H + h] +
                   v.z * k[(o0 + 2) * H + h] + v.w * k[(o0 + 3) * H + h];
#pragma unroll
        for (int off = 16; off > 0; off >>= 1) {
            qa += __shfl_down_sync(0xffffffffu, qa, off);
            ka += __shfl_down_sync(0xffffffffu, ka, off);
        }
        if (lane == 0) {
            g_qn[(size_t)wid * H + h] = qa;
            g_kn[(size_t)wid * H + h] = ka;
        }
    }
}

// ---------------------------------------------------------------------------
// CSR build (unchanged).
// ---------------------------------------------------------------------------
__global__ void csr_zero() {
    const int i = blockIdx.x * blockDim.x + threadIdx.x;
    if (i < NNODES) g_cnt[i] = 0;
}
__global__ void csr_hist(const int* __restrict__ dst, int E) {
    const int e = blockIdx.x * blockDim.x + threadIdx.x;
    if (e < E) atomicAdd(&g_cnt[dst[e]], 1);
}
__global__ void csr_scan_block() {
    __shared__ int sm[SCAN_BLK];
    const int tid = threadIdx.x;
    const int i = blockIdx.x * SCAN_BLK + tid;
    sm[tid] = (i < NNODES) ? g_cnt[i] : 0;
    __syncthreads();
    for (int off = 1; off < SCAN_BLK; off <<= 1) {
        int t = (tid >= off) ? sm[tid - off] : 0;
        __syncthreads();
        sm[tid] += t;
        __syncthreads();
    }
    if (i < NNODES) g_rowptr[i + 1] = sm[tid];
    if (tid == SCAN_BLK - 1) g_bsum[blockIdx.x] = sm[tid];
}
__global__ void csr_scan_sums() {
    __shared__ int sm[64];
    const int tid = threadIdx.x;
    const int v = (tid < SCAN_NB) ? g_bsum[tid] : 0;
    sm[tid] = v;
    __syncthreads();
    for (int off = 1; off < 64; off <<= 1) {
        int t = (tid >= off) ? sm[tid - off] : 0;
        __syncthreads();
        sm[tid] += t;
        __syncthreads();
    }
    if (tid < SCAN_NB) g_boff[tid] = sm[tid] - v;
}
__global__ void csr_scan_add() {
    const int i = blockIdx.x * blockDim.x + threadIdx.x;
    if (i < NNODES) g_rowptr[i + 1] += g_boff[i / SCAN_BLK];
    if (i == 0) g_rowptr[0] = 0;
}
__global__ void csr_cursor() {
    const int i = blockIdx.x * blockDim.x + threadIdx.x;
    if (i < NNODES) g_cursor[i] = g_rowptr[i];
}
__global__ void csr_fill(const int* __restrict__ dst, int E) {
    const int e = blockIdx.x * blockDim.x + threadIdx.x;
    if (e >= E) return;
    const int pos = atomicAdd(&g_cursor[dst[e]], 1);
    g_perm[pos] = e;
}

// ---------------------------------------------------------------------------
// Fused attention-aggregation (unchanged from R8): warp = dst node.
// ---------------------------------------------------------------------------
template <int H>
__global__ void agg_kernel(const int* __restrict__ src,
                           const int* __restrict__ et,
                           const float* __restrict__ bias, int nn) {
    const int d = (blockIdx.x * blockDim.x + threadIdx.x) >> 5;
    const int lane = threadIdx.x & 31;
    if (d >= nn) return;
    const int beg = g_rowptr[d];
    const int end = g_rowptr[d + 1];

    float m0 = -INFINITY, m1 = -INFINITY, m2 = -INFINITY, m3 = -INFINITY;

    for (int j = beg + lane; j < end; j += 32) {
        const int e = g_perm[j];
        const int s = src[e];
        const int t = et[e];
        g_packed[j] = s | (t << 17);
        if (H == 4) {
            const float4 qv = *(const float4*)&g_qn[((size_t)t * NNODES + d) * 4];
            const float4 kv = *(const float4*)&g_kn[((size_t)t * NNODES + s) * 4];
            float a0 = qv.x + kv.x, a1 = qv.y + kv.y;
            float a2 = qv.z + kv.z, a3 = qv.w + kv.w;
            a0 = a0 > 0.f ? a0 : SLOPE * a0;
            a1 = a1 > 0.f ? a1 : SLOPE * a1;
            a2 = a2 > 0.f ? a2 : SLOPE * a2;
            a3 = a3 > 0.f ? a3 : SLOPE * a3;
            *(float4*)&g_alpha[(size_t)j * 4] = make_float4(a0, a1, a2, a3);
            m0 = fmaxf(m0, a0); m1 = fmaxf(m1, a1);
            m2 = fmaxf(m2, a2); m3 = fmaxf(m3, a3);
        } else {
            float a = g_qn[(size_t)t * NNODES + d] + g_kn[(size_t)t * NNODES + s];
            a = a > 0.f ? a : SLOPE * a;
            g_alpha[j] = a;
            m0 = fmaxf(m0, a);
        }
    }
#pragma unroll
    for (int off = 16; off > 0; off >>= 1) {
        m0 = fmaxf(m0, __shfl_xor_sync(0xffffffffu, m0, off));
        if (H == 4) {
            m1 = fmaxf(m1, __shfl_xor_sync(0xffffffffu, m1, off));
            m2 = fmaxf(m2, __shfl_xor_sync(0xffffffffu, m2, off));
            m3 = fmaxf(m3, __shfl_xor_sync(0xffffffffu, m3, off));
        }
    }

    float s0 = 0.f, s1 = 0.f, s2 = 0.f, s3 = 0.f;
    for (int j = beg + lane; j < end; j += 32) {
        if (H == 4) {
            float4 al = *(const float4*)&g_alpha[(size_t)j * 4];
            al.x = expf(al.x - m0); al.y = expf(al.y - m1);
            al.z = expf(al.z - m2); al.w = expf(al.w - m3);
            *(float4*)&g_alpha[(size_t)j * 4] = al;
            s0 += al.x; s1 += al.y; s2 += al.z; s3 += al.w;
        } else {
            const float a = expf(g_alpha[j] - m0);
            g_alpha[j] = a;
            s0 += a;
        }
    }
#pragma unroll
    for (int off = 16; off > 0; off >>= 1) {
        s0 += __shfl_xor_sync(0xffffffffu, s0, off);
        if (H == 4) {
            s1 += __shfl_xor_sync(0xffffffffu, s1, off);
            s2 += __shfl_xor_sync(0xffffffffu, s2, off);
            s3 += __shfl_xor_sync(0xffffffffu, s3, off);
        }
    }
    __syncwarp();
    __threadfence_block();

    const int h = (H == 1) ? 0 : (lane >> 3);
    float sh = s0;
    if (H == 4) sh = (h & 2) ? ((h & 1) ? s3 : s2) : ((h & 1) ? s1 : s0);

    float4 acc = make_float4(0.f, 0.f, 0.f, 0.f);
    for (int j = beg; j < end; j++) {
        const int pk = g_packed[j];
        const int s_ = pk & 0x1FFFF;
        const int t_ = pk >> 17;
        const float a = g_alpha[(size_t)j * H + h];
        const float4 v = *(const float4*)
            &g_xw[((size_t)t_ * NNODES + s_) * FEAT + lane * 4];
        acc.x += a * v.x; acc.y += a * v.y;
        acc.z += a * v.z; acc.w += a * v.w;
    }
    const float inv = 1.f / (sh + 1e-16f);
    const int o = lane * 4;
    float4 r;
    r.x = acc.x * inv + bias[o + 0];
    r.y = acc.y * inv + bias[o + 1];
    r.z = acc.z * inv + bias[o + 2];
    r.w = acc.w * inv + bias[o + 3];
    r.x = r.x > 0.f ? r.x : 0.f;
    r.y = r.y > 0.f ? r.y : 0.f;
    r.z = r.z > 0.f ? r.z : 0.f;
    r.w = r.w > 0.f ? r.w : 0.f;
    *(float4*)&g_h[(size_t)d * FEAT + o] = r;
}

// ---------------------------------------------------------------------------
// Final classifier (unchanged).
// ---------------------------------------------------------------------------
__global__ void final_kernel(const float* __restrict__ Wl,
                             const float* __restrict__ bl,
                             float* __restrict__ out) {
    const int n = (blockIdx.x * blockDim.x + threadIdx.x) >> 5;
    const int lane = threadIdx.x & 31;
    if (n >= N0) return;
    const float4 v = *(const float4*)&g_h[(size_t)n * FEAT + lane * 4];
#pragma unroll
    for (int l = 0; l < LAB; l++) {
        const float4 w = *(const float4*)&Wl[l * FEAT + lane * 4];
        float p = v.x * w.x + v.y * w.y + v.z * w.z + v.w * w.w;
#pragma unroll
        for (int off = 16; off > 0; off >>= 1)
            p += __shfl_down_sync(0xffffffffu, p, off);
        if (lane == 0) out[n * LAB + l] = p + bl[l];
    }
}

// ---------------------------------------------------------------------------
// Launcher: ONLY kernel launches.
// ---------------------------------------------------------------------------
extern "C" void kernel_launch(void* const* d_in, const int* in_sizes, int n_in,
                              void* d_out, int out_size) {
    const float* x0  = (const float*)d_in[0];
    const float* x1  = (const float*)d_in[1];
    const float* x2  = (const float*)d_in[2];
    const int*   ei  = (const int*)  d_in[3];
    const int*   et  = (const int*)  d_in[4];
    const float* Wp0 = (const float*)d_in[5];
    const float* bp0 = (const float*)d_in[6];
    const float* Wp1 = (const float*)d_in[7];
    const float* bp1 = (const float*)d_in[8];
    const float* Wp2 = (const float*)d_in[9];
    const float* bp2 = (const float*)d_in[10];
    const float* W1  = (const float*)d_in[11];
    const float* q1  = (const float*)d_in[12];
    const float* k1  = (const float*)d_in[13];
    const float* b1  = (const float*)d_in[14];
    const float* W2  = (const float*)d_in[15];
    const float* q2  = (const float*)d_in[16];
    const float* k2  = (const float*)d_in[17];
    const float* b2  = (const float*)d_in[18];
    const float* Wl  = (const float*)d_in[19];
    const float* bl  = (const float*)d_in[20];
    float* out = (float*)d_out;

    const int E = in_sizes[4];          // 400000
    const int* srcp = ei;
    const int* dstp = ei + E;

    const int TPB = 256;

    // --- fused projections: one launch, blockIdx.z = omic ---
    {
        dim3 g((N0 + 127) / 128, PROJ / 128, 3);
        gemm128<1><<<g, TPB>>>(x0, x1, x2, Wp0, Wp1, Wp2, bp0, bp1, bp2,
                               2000, 1500, 1000, N0, 0);
    }

    // --- CSR build ---
    {
        const int nb_n = (NNODES + TPB - 1) / TPB;
        const int nb_e = (E + TPB - 1) / TPB;
        csr_zero<<<nb_n, TPB>>>();
        csr_hist<<<nb_e, TPB>>>(dstp, E);
        csr_scan_block<<<SCAN_NB, SCAN_BLK>>>();
        csr_scan_sums<<<1, 64>>>();
        csr_scan_add<<<nb_n, TPB>>>();
        csr_cursor<<<nb_n, TPB>>>();
        csr_fill<<<nb_e, TPB>>>(dstp, E);
    }

    const int nrows = RNUM * NNODES;
    const int qk_blocks = (nrows * 32 + TPB - 1) / TPB;

    // --- layer 1 ---
    {
        dim3 g((NNODES + 127) / 128, 1, RNUM);
        gemm128<0><<<g, TPB>>>(nullptr, nullptr, nullptr, W1, nullptr, nullptr,
                               nullptr, nullptr, nullptr, PROJ, 0, 0, NNODES, 1);
    }
    qk_kernel<HEADS1><<<qk_blocks, TPB>>>(q1, k1, nrows);
    agg_kernel<HEADS1><<<(NNODES * 32 + TPB - 1) / TPB, TPB>>>(srcp, et, b1, NNODES);

    // --- layer 2 (only dst < N0 matter for the final classifier) ---
    {
        dim3 g((NNODES + 127) / 128, 1, RNUM);
        gemm128<0><<<g, TPB>>>(nullptr, nullptr, nullptr, W2, nullptr, nullptr,
                               nullptr, nullptr, nullptr, FEAT, 0, 0, NNODES, 2);
    }
    qk_kernel<1><<<qk_blocks, TPB>>>(q2, k2, nrows);
    agg_kernel<1><<<(N0 * 32 + TPB - 1) / TPB, TPB>>>(srcp, et, b2, N0);

    // --- classifier ---
    final_kernel<<<(N0 * 32 + TPB - 1) / TPB, TPB>>>(Wl, bl, out);
}